// round 12
// baseline (speedup 1.0000x reference)
#include <cuda_runtime.h>
#include <cuda_bf16.h>
#include <math.h>
#include <stdint.h>

#define Bn   256
#define Tn   512
#define NT   (Bn*Tn)          // 131072 tokens

// tcgemm smem: 2 stages x 4 tiles of [128][64] bf16 (SW128) + bias
#define TCG_STAGE  65536
#define OFF_BIAS   131072
#define SMEM_TC    (131072 + 512)

// GRU smem (bytes)
#define OFF_WH   0                    // Whh hi  [4 chunks][128 rows][64] bf16
#define OFF_WL   65536                // Whh lo
#define OFF_AH2  131072               // h hi    [4 chunks][32 rows][64] bf16
#define OFF_AL2  147456               // h lo
#define OFF_MBAR 163840               // mbarrier u64
#define SMEM_G3  163904

// ----------------- device scratch (bss-zeroed at module load) -----------------
__device__ float g_xw  [(size_t)NT*1536];   // input-gate precompute, reused per layer
__device__ float g_bufB[(size_t)NT*512];    // final-layer fp32 activations (pool input)
__device__ int   g_perm[256];               // batch order sorted by length desc
__device__ __nv_bfloat16 g_ah[(size_t)NT*512];   // A hi split (GEMM input)
__device__ __nv_bfloat16 g_al[(size_t)NT*512];   // A lo split
__device__ __nv_bfloat16 g_wh[5*1536*512];       // W hi split, per-layer slots
__device__ __nv_bfloat16 g_wl[5*1536*512];       // W lo split
// h exchange in A-tile layout: [pp][dir][bt][chunk4][row32][col64] bf16
__device__ __nv_bfloat16 g_hxh[2*2*8*4*32*64];
__device__ __nv_bfloat16 g_hxl[2*2*8*4*32*64];

// ----------------- mma.sync helpers (base ISA, compiles at compute_103) -----------------
__device__ __forceinline__ uint32_t smem_u32(const void* p) {
    uint32_t a;
    asm("{ .reg .u64 t; cvta.to.shared.u64 t, %1; cvt.u32.u64 %0, t; }" : "=r"(a) : "l"(p));
    return a;
}
#define SWIZ128(b) ((b) ^ (((b) >> 3) & 0x70))

__device__ __forceinline__ void ldsm4(uint32_t* r, uint32_t addr) {
    asm volatile("ldmatrix.sync.aligned.m8n8.x4.shared.b16 {%0,%1,%2,%3}, [%4];"
                 : "=r"(r[0]), "=r"(r[1]), "=r"(r[2]), "=r"(r[3]) : "r"(addr));
}
__device__ __forceinline__ void ldsm2(uint32_t* r, uint32_t addr) {
    asm volatile("ldmatrix.sync.aligned.m8n8.x2.shared.b16 {%0,%1}, [%2];"
                 : "=r"(r[0]), "=r"(r[1]) : "r"(addr));
}
__device__ __forceinline__ void mma16816(float* c, const uint32_t* a, const uint32_t* b) {
    asm volatile("mma.sync.aligned.m16n8k16.row.col.f32.bf16.bf16.f32 "
                 "{%0,%1,%2,%3}, {%4,%5,%6,%7}, {%8,%9}, {%0,%1,%2,%3};"
                 : "+f"(c[0]), "+f"(c[1]), "+f"(c[2]), "+f"(c[3])
                 : "r"(a[0]), "r"(a[1]), "r"(a[2]), "r"(a[3]), "r"(b[0]), "r"(b[1]));
}
__device__ __forceinline__ void cp16(uint32_t dst, const void* src) {
    asm volatile("cp.async.cg.shared.global [%0], [%1], 16;" :: "r"(dst), "l"(src) : "memory");
}

// fast gates: MUFU-based sigmoid/tanh (err ~1e-6, saturates correctly)
__device__ __forceinline__ float fsig(float x) {
    return __fdividef(1.f, 1.f + __expf(-x));
}
__device__ __forceinline__ float ftanh(float x) {
    return __fdividef(2.f, 1.f + __expf(-2.f*x)) - 1.f;
}

// cluster mbarrier wait (acquire, cluster scope)
#define MBAR_WAITC(mbar, par) do {                                             \
    uint32_t _m = (uint32_t)(mbar); uint32_t _p = (uint32_t)(par);             \
    asm volatile(                                                              \
        "{\n\t.reg .pred P1;\n\t"                                              \
        "WL_%=:\n\t"                                                           \
        "mbarrier.try_wait.parity.acquire.cluster.shared::cta.b64 P1, [%0], %1, 0x989680;\n\t" \
        "@P1 bra.uni WD_%=;\n\t"                                               \
        "bra.uni WL_%=;\n\t"                                                   \
        "WD_%=:\n\t}"                                                          \
        :: "r"(_m), "r"(_p) : "memory");                                       \
} while (0)

// ----------------- sort batch indices by length descending -----------------
__global__ void halt_sort_perm(const int* __restrict__ lengths) {
    __shared__ int key[256];
    __shared__ int idx[256];
    int tid = threadIdx.x;
    key[tid] = -lengths[tid];
    idx[tid] = tid;
    __syncthreads();
    for (int k = 2; k <= 256; k <<= 1)
        for (int j = k >> 1; j > 0; j >>= 1) {
            int ixj = tid ^ j;
            if (ixj > tid) {
                bool asc = ((tid & k) == 0);
                int a = key[tid], c = key[ixj];
                bool gt = a > c;
                if (asc == gt) {
                    key[tid] = c; key[ixj] = a;
                    int t2 = idx[tid]; idx[tid] = idx[ixj]; idx[ixj] = t2;
                }
            }
            __syncthreads();
        }
    g_perm[tid] = idx[tid];
}

// ----------------- input projection: LN -> Linear -> GELU -> Linear, writes bf16 hi/lo -----------------
__global__ void halt_proj(const float* __restrict__ x, const int* __restrict__ lengths,
                          const float* __restrict__ ln_g, const float* __restrict__ ln_b,
                          const float* __restrict__ w1, const float* __restrict__ b1,
                          const float* __restrict__ w2, const float* __restrict__ b2) {
    int token = blockIdx.x;
    int b = token >> 9, t = token & 511;
    if (t >= lengths[b]) return;
    __shared__ float sx[25], sn[25], sh1[128];
    int tid = threadIdx.x;
    if (tid < 25) sx[tid] = x[(size_t)token*25 + tid];
    __syncthreads();
    float mu = 0.f;
#pragma unroll
    for (int i = 0; i < 25; i++) mu += sx[i];
    mu *= (1.0f/25.0f);
    float var = 0.f;
#pragma unroll
    for (int i = 0; i < 25; i++) { float d = sx[i]-mu; var += d*d; }
    var *= (1.0f/25.0f);
    float rstd = rsqrtf(var + 1e-5f);
    if (tid < 25) sn[tid] = (sx[tid]-mu)*rstd*ln_g[tid] + ln_b[tid];
    __syncthreads();
    float a = b1[tid];
#pragma unroll
    for (int i = 0; i < 25; i++) a += sn[i]*w1[i*128 + tid];
    float ge = 0.5f*a*(1.0f + erff(a*0.70710678118654752440f));
    sh1[tid] = ge;
    __syncthreads();
    float o = b2[tid];
#pragma unroll 8
    for (int i = 0; i < 128; i++) o += sh1[i]*__ldg(&w2[i*128 + tid]);
    __nv_bfloat16 hbf = __float2bfloat16(o);
    g_ah[(size_t)token*128 + tid] = hbf;
    g_al[(size_t)token*128 + tid] = __float2bfloat16(o - __bfloat162float(hbf));
}

// ----------------- fp32 -> bf16 hi/lo split (weights; per-layer slots) -----------------
__global__ void halt_cvt(const float* __restrict__ src, __nv_bfloat16* __restrict__ hi,
                         __nv_bfloat16* __restrict__ lo, size_t n) {
    size_t i = (size_t)blockIdx.x*256 + threadIdx.x;
    if (i >= n) return;
    float v = src[i];
    __nv_bfloat16 h = __float2bfloat16(v);
    hi[i] = h;
    lo[i] = __float2bfloat16(v - __bfloat162float(h));
}

// ----------------- mma.sync GEMM with cp.async 2-stage pipeline -----------------
__global__ __launch_bounds__(256)
void halt_tcgemm(int K, const __nv_bfloat16* __restrict__ wh, const __nv_bfloat16* __restrict__ wl,
                 const float* __restrict__ bias, const int* __restrict__ lengths) {
    int m0 = blockIdx.x * 128;
    int n0 = blockIdx.y * 128;
    if ((m0 & 511) >= lengths[m0 >> 9]) return;   // fully-padded tile: outputs never read
    extern __shared__ char smem[];
    uint32_t sb = smem_u32(smem);
    int tid = threadIdx.x, warp = tid >> 5, lane = tid & 31;
    int wm = warp & 3, wn = warp >> 2;             // 4 x 2 warp grid, tile 32x64

    if (tid < 128) ((float*)(smem + OFF_BIAS))[tid] = bias[n0 + tid];

    const char* pAh = (const char*)g_ah;
    const char* pAl = (const char*)g_al;
    const char* pBh = (const char*)wh;
    const char* pBl = (const char*)wl;

    float acc[2][8][4];
#pragma unroll
    for (int mi = 0; mi < 2; mi++)
#pragma unroll
        for (int ni = 0; ni < 8; ni++)
#pragma unroll
            for (int q = 0; q < 4; q++) acc[mi][ni][q] = 0.f;

    int arow = wm*32 + (lane & 15);
    int acolsel = (lane >> 4) * 8;
    int brow = wn*64 + (lane & 7) + ((lane & 16) ? 8 : 0);
    int bcolsel = (lane & 8) ? 8 : 0;

    int nchunks = K >> 6;
    auto stage = [&](int c, int buf) {
        uint32_t base = sb + buf*TCG_STAGE;
        for (int it = tid; it < 1024; it += 256) {
            int r = it >> 3, u = it & 7;
            uint32_t sw = SWIZ128((uint32_t)(r*128 + u*16));
            size_t ga = ((size_t)(m0 + r)*K + c*64)*2 + u*16;
            size_t gb = ((size_t)(n0 + r)*K + c*64)*2 + u*16;
            cp16(base + 0     + sw, pAh + ga);
            cp16(base + 16384 + sw, pAl + ga);
            cp16(base + 32768 + sw, pBh + gb);
            cp16(base + 49152 + sw, pBl + gb);
        }
        asm volatile("cp.async.commit_group;" ::: "memory");
    };

    stage(0, 0);
    for (int c = 0; c < nchunks; c++) {
        int buf = c & 1;
        if (c + 1 < nchunks) {
            stage(c + 1, buf ^ 1);
            asm volatile("cp.async.wait_group 1;" ::: "memory");
        } else {
            asm volatile("cp.async.wait_group 0;" ::: "memory");
        }
        __syncthreads();
        uint32_t base = sb + buf*TCG_STAGE;
#pragma unroll
        for (int ks = 0; ks < 4; ks++) {
            int kc = ks*16;
            uint32_t ah[2][4], al[2][4];
#pragma unroll
            for (int mi = 0; mi < 2; mi++) {
                uint32_t off = SWIZ128((uint32_t)((arow + mi*16)*128 + (kc + acolsel)*2));
                ldsm4(ah[mi], base + 0     + off);
                ldsm4(al[mi], base + 16384 + off);
            }
            uint32_t bh[4][4], bl[4][4];
#pragma unroll
            for (int p = 0; p < 4; p++) {
                uint32_t off = SWIZ128((uint32_t)((brow + p*16)*128 + (kc + bcolsel)*2));
                ldsm4(bh[p], base + 32768 + off);
                ldsm4(bl[p], base + 49152 + off);
            }
#pragma unroll
            for (int mi = 0; mi < 2; mi++)
#pragma unroll
                for (int p = 0; p < 4; p++) {
                    mma16816(acc[mi][2*p],   ah[mi], &bh[p][0]);
                    mma16816(acc[mi][2*p],   ah[mi], &bl[p][0]);
                    mma16816(acc[mi][2*p],   al[mi], &bh[p][0]);
                    mma16816(acc[mi][2*p+1], ah[mi], &bh[p][2]);
                    mma16816(acc[mi][2*p+1], ah[mi], &bl[p][2]);
                    mma16816(acc[mi][2*p+1], al[mi], &bh[p][2]);
                }
        }
        __syncthreads();
    }

    const float* sbias = (const float*)(smem + OFF_BIAS);
#pragma unroll
    for (int mi = 0; mi < 2; mi++) {
        int rw = m0 + wm*32 + mi*16 + (lane >> 2);
#pragma unroll
        for (int ni = 0; ni < 8; ni++) {
            int cw = wn*64 + ni*8 + (lane & 3)*2;
            float bx = sbias[cw], by = sbias[cw + 1];
            float2 v0 = { acc[mi][ni][0] + bx, acc[mi][ni][1] + by };
            float2 v1 = { acc[mi][ni][2] + bx, acc[mi][ni][3] + by };
            *(float2*)&g_xw[(size_t)rw*1536 + n0 + cw]       = v0;
            *(float2*)&g_xw[(size_t)(rw + 8)*1536 + n0 + cw] = v1;
        }
    }
}

// ----------------- GRU v5: gate-aligned fragments, register gates, mbarrier cluster sync --------
// 128 blocks = 2 dir x 8 bt x 8 hc(32 j); cluster = 8 hc blocks of one (dir,bt).
// Warp: wm=warp>>2 (sample half, m16), wn=warp&3 (8 j cols); 3 gate n8-tiles share (sample,j).
__global__ __launch_bounds__(256, 1) __cluster_dims__(8, 1, 1)
void halt_gru3(const float* __restrict__ xw, float* __restrict__ y,
               const float* __restrict__ Whh, const float* __restrict__ bhh,
               const int* __restrict__ lengths, int last) {
    extern __shared__ char smg[];
    uint32_t sb = smem_u32(smg);
    int grp = blockIdx.x >> 3;
    int hc  = blockIdx.x & 7;
    int dir = grp >> 3;
    int bt  = grp & 7;
    int j0  = hc * 32;
    int tid = threadIdx.x;
    int warp = tid >> 5, lane = tid & 31;
    int wm = warp >> 2, wn = warp & 3;

    // load Whh slice -> smem bf16 hi/lo, [4 chunks][96 rows][64], SW128
    const float* Wd = Whh + (size_t)dir*768*256;
    for (int idx = tid; idx < 96*256; idx += 256) {
        int r = idx >> 8, k = idx & 255;
        int g = r >> 5, jl = r & 31;
        float w = Wd[(size_t)(g*256 + j0 + jl)*256 + k];
        __nv_bfloat16 h = __float2bfloat16(w);
        __nv_bfloat16 l = __float2bfloat16(w - __bfloat162float(h));
        int chunk = k >> 6;
        uint32_t sw = SWIZ128((uint32_t)(r*128 + (k & 63)*2));
        *(__nv_bfloat16*)(smg + OFF_WH + chunk*16384 + sw) = h;
        *(__nv_bfloat16*)(smg + OFF_WL + chunk*16384 + sw) = l;
    }
    if (tid == 0) {
        asm volatile("mbarrier.init.shared.b64 [%0], 8;" :: "r"(sb + OFF_MBAR) : "memory");
    }
    __syncthreads();
    // cluster sync once: peers' mbarrier init visible before any remote arrive
    asm volatile("barrier.cluster.arrive.aligned;" ::: "memory");
    asm volatile("barrier.cluster.wait.aligned;"   ::: "memory");

    // element mapping: thread owns (s_a, jc), (s_a, jc+1), (s_b, jc), (s_b, jc+1)
    int sa = wm*16 + (lane >> 2);          // local sample row (s_b = sa+8)
    int jc = wn*8 + (lane & 3)*2;          // local j col (pair jc, jc+1)
    int jcg = j0 + jc;                     // global j within dir's 256
    float bhr0 = bhh[dir*768 +       jcg], bhr1 = bhh[dir*768 +       jcg + 1];
    float bhz0 = bhh[dir*768 + 256 + jcg], bhz1 = bhh[dir*768 + 256 + jcg + 1];
    float bhn0 = bhh[dir*768 + 512 + jcg], bhn1 = bhh[dir*768 + 512 + jcg + 1];
    int pb2[2], lenv2[2];
#pragma unroll
    for (int si = 0; si < 2; si++) {
        pb2[si]   = g_perm[bt*32 + sa + si*8];
        lenv2[si] = lengths[pb2[si]];
    }
    int tmax = lengths[g_perm[bt*32]];     // sorted desc -> same across cluster

    // cache static B-hi weight fragments in regs: [16 k16][3 gates][2]
    int lx = lane & 15;
    int brx = lx & 7, bsel = (lx & 8) ? 8 : 0;
    uint32_t Bh[16][6];
#pragma unroll
    for (int k16 = 0; k16 < 16; k16++) {
        int chunk = k16 >> 2, kc = (k16 & 3)*16;
#pragma unroll
        for (int g = 0; g < 3; g++) {
            uint32_t off = SWIZ128((uint32_t)((g*32 + wn*8 + brx)*128 + (kc + bsel)*2));
            ldsm2(&Bh[k16][g*2], sb + OFF_WH + chunk*16384 + off);
        }
    }

    int arow = wm*16 + (lane & 15);
    int acolsel = (lane >> 4) * 8;
    int jchunk = jcg >> 6;
    uint32_t swout = SWIZ128((uint32_t)(0*128 + (jcg & 63)*2));  // per-sample add s*128 later

    float hprev[4] = {0.f, 0.f, 0.f, 0.f};

    // xw prefetch (one step ahead)
    float2 xr[2], xz[2], xn[2];
    int tok[2];
    auto pref = [&](int tt, float2* pr, float2* pz, float2* pn, int* tk) {
#pragma unroll
        for (int si = 0; si < 2; si++) {
            tk[si] = 0;
            if (tt < lenv2[si]) {
                tk[si] = dir ? (lenv2[si] - 1 - tt) : tt;
                const float* xq = xw + ((size_t)pb2[si]*512 + tk[si])*1536 + dir*768 + jcg;
                pr[si] = *(const float2*)xq;
                pz[si] = *(const float2*)(xq + 256);
                pn[si] = *(const float2*)(xq + 512);
            }
        }
    };
    pref(0, xr, xz, xn, tok);

    for (int t = 0; t < tmax; t++) {
        if (t > 0) MBAR_WAITC(sb + OFF_MBAR, (t - 1) & 1);

        // phase 1: copy peer-written A tiles (already swizzled layout)
        size_t tb = ((size_t)((t & 1)*2 + dir)*8 + bt) * 16384;
        const uint4* srch = (const uint4*)((const char*)g_hxh + tb);
        const uint4* srcl = (const uint4*)((const char*)g_hxl + tb);
#pragma unroll
        for (int q = 0; q < 4; q++) {
            int it = tid + q*256;
            uint4 vh = __ldcg(&srch[it]);
            uint4 vl = __ldcg(&srcl[it]);
            *(uint4*)(smg + OFF_AH2 + it*16) = vh;
            *(uint4*)(smg + OFF_AL2 + it*16) = vl;
        }
        __syncthreads();

        // phase 2: mma — A ldsm + B-lo ldsm2, B-hi from registers; gate-aligned acc
        float acc[3][4];
#pragma unroll
        for (int g = 0; g < 3; g++) { acc[g][0]=0.f; acc[g][1]=0.f; acc[g][2]=0.f; acc[g][3]=0.f; }
#pragma unroll
        for (int k16 = 0; k16 < 16; k16++) {
            int chunk = k16 >> 2, kc = (k16 & 3)*16;
            uint32_t asw = SWIZ128((uint32_t)(arow*128 + (kc + acolsel)*2));
            uint32_t ah[4], al[4];
            ldsm4(ah, sb + OFF_AH2 + chunk*4096 + asw);
            ldsm4(al, sb + OFF_AL2 + chunk*4096 + asw);
            uint32_t bl[6];
#pragma unroll
            for (int g = 0; g < 3; g++) {
                uint32_t off = SWIZ128((uint32_t)((g*32 + wn*8 + brx)*128 + (kc + bsel)*2));
                ldsm2(&bl[g*2], sb + OFF_WL + chunk*16384 + off);
            }
#pragma unroll
            for (int g = 0; g < 3; g++) {
                mma16816(acc[g], ah, &Bh[k16][g*2]);
                mma16816(acc[g], ah, &bl[g*2]);
                mma16816(acc[g], al, &Bh[k16][g*2]);
            }
        }

        // prefetch xw for NEXT step (lands during sync + next phases)
        float2 nr[2], nz[2], nn2[2];
        int ntok[2];
        pref(t + 1, nr, nz, nn2, ntok);

        // phase 3: gates in registers; update hprev; store exchange + next-layer A (or y)
        size_t tbn = ((size_t)(((t+1) & 1)*2 + dir)*8 + bt) * 16384;
#pragma unroll
        for (int si = 0; si < 2; si++) {
            if (t < lenv2[si]) {
                int e = si*2;
                int s = sa + si*8;
                float r0 = fsig(xr[si].x + acc[0][e]   + bhr0);
                float r1 = fsig(xr[si].y + acc[0][e+1] + bhr1);
                float z0 = fsig(xz[si].x + acc[1][e]   + bhz0);
                float z1 = fsig(xz[si].y + acc[1][e+1] + bhz1);
                float n0 = ftanh(xn[si].x + r0*(acc[2][e]   + bhn0));
                float n1 = ftanh(xn[si].y + r1*(acc[2][e+1] + bhn1));
                float h0 = (1.f - z0)*n0 + z0*hprev[e];
                float h1 = (1.f - z1)*n1 + z1*hprev[e+1];
                hprev[e] = h0; hprev[e+1] = h1;
                __nv_bfloat16 hb0 = __float2bfloat16(h0);
                __nv_bfloat16 hb1 = __float2bfloat16(h1);
                __nv_bfloat16 lb0 = __float2bfloat16(h0 - __bfloat162float(hb0));
                __nv_bfloat16 lb1 = __float2bfloat16(h1 - __bfloat162float(hb1));
                uint32_t hp = (uint32_t)__bfloat16_as_ushort(hb0) | ((uint32_t)__bfloat16_as_ushort(hb1) << 16);
                uint32_t lp = (uint32_t)__bfloat16_as_ushort(lb0) | ((uint32_t)__bfloat16_as_ushort(lb1) << 16);
                uint32_t sw = SWIZ128((uint32_t)(s*128 + (jcg & 63)*2));
                *(uint32_t*)((char*)g_hxh + tbn + jchunk*4096 + sw) = hp;
                *(uint32_t*)((char*)g_hxl + tbn + jchunk*4096 + sw) = lp;
                size_t oc = ((size_t)pb2[si]*512 + tok[si])*512 + dir*256 + jcg;
                if (last) {
                    *(float2*)&y[oc] = make_float2(h0, h1);
                } else {
                    *(uint32_t*)&g_ah[oc] = hp;
                    *(uint32_t*)&g_al[oc] = lp;
                }
            }
        }
        __syncthreads();   // all block stores ordered before tid0's release-arrive
        if (tid == 0 && t + 1 < tmax) {
#pragma unroll
            for (int rk = 0; rk < 8; rk++) {
                uint32_t rem;
                asm volatile("mapa.shared::cluster.u32 %0, %1, %2;"
                             : "=r"(rem) : "r"(sb + OFF_MBAR), "r"(rk));
                asm volatile("mbarrier.arrive.release.cluster.shared::cluster.b64 _, [%0];"
                             :: "r"(rem) : "memory");
            }
        }
#pragma unroll
        for (int si = 0; si < 2; si++) {
            xr[si] = nr[si]; xz[si] = nz[si]; xn[si] = nn2[si]; tok[si] = ntok[si];
        }
    }
    // hold cluster resident until all remote arrives have landed
    asm volatile("barrier.cluster.arrive.aligned;" ::: "memory");
    asm volatile("barrier.cluster.wait.aligned;"   ::: "memory");
}

// ----------------- top-k pooling + classifier -----------------
__global__ __launch_bounds__(256)
void halt_pool(const float* __restrict__ H, const int* __restrict__ lengths,
               const float* __restrict__ Wc, const float* __restrict__ bc,
               float* __restrict__ out) {
    int b = blockIdx.x, tid = threadIdx.x;
    __shared__ float ns[512];
    __shared__ int   si[512];
    __shared__ float red[256];
    int len = lengths[b];
    int warp = tid >> 5, lane = tid & 31;
    for (int r = warp; r < 512; r += 8) {
        float sc = 1e9f;
        if (r < len) {
            const float* row = H + ((size_t)b*512 + r)*512;
            float acc = 0.f;
#pragma unroll 4
            for (int d = lane; d < 512; d += 32) { float v = row[d]; acc += v*v; }
#pragma unroll
            for (int o = 16; o > 0; o >>= 1) acc += __shfl_xor_sync(0xffffffffu, acc, o);
            sc = -sqrtf(acc);
        }
        if (lane == 0) { ns[r] = sc; si[r] = r; }
    }
    __syncthreads();
    for (int k = 2; k <= 512; k <<= 1)
        for (int j = k >> 1; j > 0; j >>= 1) {
            for (int i = tid; i < 512; i += 256) {
                int ixj = i ^ j;
                if (ixj > i) {
                    bool asc = ((i & k) == 0);
                    float a = ns[i], c = ns[ixj];
                    int ia = si[i], ic = si[ixj];
                    bool gt = (a > c) || (a == c && ia > ic);
                    if (asc == gt) { ns[i] = c; ns[ixj] = a; si[i] = ic; si[ixj] = ia; }
                }
            }
            __syncthreads();
        }
    int kk = (int)ceilf((float)len * 0.15f);
    if (kk < 1) kk = 1;
    float a0 = 0.f, a1 = 0.f;
    for (int i = 0; i < kk; i++) {
        int r = si[i];
        const float* row = H + ((size_t)b*512 + r)*512;
        a0 += row[tid]; a1 += row[tid + 256];
    }
    float kf = (float)kk;
    float part = (a0/kf)*Wc[tid] + (a1/kf)*Wc[tid + 256];
    red[tid] = part;
    __syncthreads();
    for (int s2 = 128; s2 > 0; s2 >>= 1) {
        if (tid < s2) red[tid] += red[tid + s2];
        __syncthreads();
    }
    if (tid == 0) out[b] = red[0] + bc[0];
}

// ----------------- host orchestration -----------------
extern "C" void kernel_launch(void* const* d_in, const int* in_sizes, int n_in,
                              void* d_out, int out_size) {
    const float* x    = (const float*)d_in[0];
    const int*   lens = (const int*)  d_in[1];
    const float* ln_g = (const float*)d_in[2];
    const float* ln_b = (const float*)d_in[3];
    const float* w1   = (const float*)d_in[4];
    const float* b1   = (const float*)d_in[5];
    const float* w2   = (const float*)d_in[6];
    const float* b2   = (const float*)d_in[7];
    const float* Wih0 = (const float*)d_in[8];
    const float* Whh0 = (const float*)d_in[9];
    const float* bih0 = (const float*)d_in[10];
    const float* bhh0 = (const float*)d_in[11];
    const float* Wih  = (const float*)d_in[12];
    const float* Whh  = (const float*)d_in[13];
    const float* bih  = (const float*)d_in[14];
    const float* bhh  = (const float*)d_in[15];
    const float* Wc   = (const float*)d_in[16];
    const float* bc   = (const float*)d_in[17];
    float* out = (float*)d_out;

    cudaFuncSetAttribute(halt_gru3, cudaFuncAttributeMaxDynamicSharedMemorySize, SMEM_G3);
    cudaFuncSetAttribute(halt_tcgemm, cudaFuncAttributeMaxDynamicSharedMemorySize, SMEM_TC);

    void *pB = 0, *pxw = 0, *pwh = 0, *pwl = 0, *phxh = 0, *phxl = 0;
    cudaGetSymbolAddress(&pB,   g_bufB);
    cudaGetSymbolAddress(&pxw,  g_xw);
    cudaGetSymbolAddress(&pwh,  g_wh);
    cudaGetSymbolAddress(&pwl,  g_wl);
    cudaGetSymbolAddress(&phxh, g_hxh);
    cudaGetSymbolAddress(&phxl, g_hxl);
    float* fB  = (float*)pB;
    float* fxw = (float*)pxw;

    halt_sort_perm<<<1, 256>>>(lens);
    halt_proj<<<NT, 128>>>(x, lens, ln_g, ln_b, w1, b1, w2, b2);

    for (int l = 0; l < 5; l++) {
        const float* Wi = l ? (Wih + (size_t)(l-1)*2*768*512) : Wih0;
        int K = l ? 512 : 128;
        size_t nW = (size_t)1536 * K;
        __nv_bfloat16* wh = (__nv_bfloat16*)pwh + (size_t)l*1536*512;
        __nv_bfloat16* wl = (__nv_bfloat16*)pwl + (size_t)l*1536*512;
        halt_cvt<<<(unsigned)((nW + 255)/256), 256>>>(Wi, wh, wl, nW);
    }

    for (int l = 0; l < 5; l++) {
        const float* bi = l ? (bih + (l-1)*1536) : bih0;
        const float* Wh = l ? (Whh + (size_t)(l-1)*2*768*256) : Whh0;
        const float* bh = l ? (bhh + (l-1)*1536) : bhh0;
        int K = l ? 512 : 128;
        const __nv_bfloat16* wh = (const __nv_bfloat16*)pwh + (size_t)l*1536*512;
        const __nv_bfloat16* wl = (const __nv_bfloat16*)pwl + (size_t)l*1536*512;

        cudaMemsetAsync(phxh, 0, (size_t)2*2*8*4*32*64*sizeof(__nv_bfloat16));
        cudaMemsetAsync(phxl, 0, (size_t)2*2*8*4*32*64*sizeof(__nv_bfloat16));

        dim3 gg(NT/128, 12);
        halt_tcgemm<<<gg, 256, SMEM_TC>>>(K, wh, wl, bi, lens);

        halt_gru3<<<128, 256, SMEM_G3>>>(fxw, fB, Wh, bh, lens, (l == 4) ? 1 : 0);
    }
    halt_pool<<<256, 256>>>(fB, lens, Wc, bc, out);
}

// round 13
// speedup vs baseline: 1.2533x; 1.2533x over previous
#include <cuda_runtime.h>
#include <cuda_bf16.h>
#include <math.h>
#include <stdint.h>

#define Bn   256
#define Tn   512
#define NT   (Bn*Tn)          // 131072 tokens

// tcgemm smem: 2 stages x 4 tiles of [128][64] bf16 (SW128) + bias
#define TCG_STAGE  65536
#define OFF_BIAS   131072
#define SMEM_TC    (131072 + 512)

// GRU smem (bytes)
#define OFF_WH   0                    // Whh hi  [4 chunks][96 rows][64] bf16
#define OFF_WL   65536                // Whh lo
#define OFF_AH2  131072               // h hi    [4 chunks][32 rows][64] bf16
#define OFF_AL2  147456               // h lo
#define SMEM_G3  163840

// ----------------- device scratch (bss-zeroed at module load) -----------------
__device__ float g_xw  [(size_t)NT*1536];   // input-gate precompute, reused per layer
__device__ float g_bufB[(size_t)NT*512];    // final-layer fp32 activations (pool input)
__device__ int   g_perm[256];               // batch order sorted by length desc
__device__ __nv_bfloat16 g_ah[(size_t)NT*512];   // A hi split (GEMM input)
__device__ __nv_bfloat16 g_al[(size_t)NT*512];   // A lo split
__device__ __nv_bfloat16 g_wh[5*1536*512];       // W hi split, per-layer slots
__device__ __nv_bfloat16 g_wl[5*1536*512];       // W lo split
// h exchange in A-tile layout: [pp][dir][bt][chunk4][row32][col64] bf16
__device__ __nv_bfloat16 g_hxh[2*2*8*4*32*64];
__device__ __nv_bfloat16 g_hxl[2*2*8*4*32*64];

// ----------------- mma.sync helpers (base ISA, compiles at compute_103) -----------------
__device__ __forceinline__ uint32_t smem_u32(const void* p) {
    uint32_t a;
    asm("{ .reg .u64 t; cvta.to.shared.u64 t, %1; cvt.u32.u64 %0, t; }" : "=r"(a) : "l"(p));
    return a;
}
#define SWIZ128(b) ((b) ^ (((b) >> 3) & 0x70))

__device__ __forceinline__ void ldsm4(uint32_t* r, uint32_t addr) {
    asm volatile("ldmatrix.sync.aligned.m8n8.x4.shared.b16 {%0,%1,%2,%3}, [%4];"
                 : "=r"(r[0]), "=r"(r[1]), "=r"(r[2]), "=r"(r[3]) : "r"(addr));
}
__device__ __forceinline__ void ldsm2(uint32_t* r, uint32_t addr) {
    asm volatile("ldmatrix.sync.aligned.m8n8.x2.shared.b16 {%0,%1}, [%2];"
                 : "=r"(r[0]), "=r"(r[1]) : "r"(addr));
}
__device__ __forceinline__ void mma16816(float* c, const uint32_t* a, const uint32_t* b) {
    asm volatile("mma.sync.aligned.m16n8k16.row.col.f32.bf16.bf16.f32 "
                 "{%0,%1,%2,%3}, {%4,%5,%6,%7}, {%8,%9}, {%0,%1,%2,%3};"
                 : "+f"(c[0]), "+f"(c[1]), "+f"(c[2]), "+f"(c[3])
                 : "r"(a[0]), "r"(a[1]), "r"(a[2]), "r"(a[3]), "r"(b[0]), "r"(b[1]));
}
__device__ __forceinline__ void cp16(uint32_t dst, const void* src) {
    asm volatile("cp.async.cg.shared.global [%0], [%1], 16;" :: "r"(dst), "l"(src) : "memory");
}

// fast gates: MUFU-based sigmoid/tanh (err ~1e-6, saturates correctly)
__device__ __forceinline__ float fsig(float x) {
    return __fdividef(1.f, 1.f + __expf(-x));
}
__device__ __forceinline__ float ftanh(float x) {
    return __fdividef(2.f, 1.f + __expf(-2.f*x)) - 1.f;
}

// ----------------- sort batch indices by length descending -----------------
__global__ void halt_sort_perm(const int* __restrict__ lengths) {
    __shared__ int key[256];
    __shared__ int idx[256];
    int tid = threadIdx.x;
    key[tid] = -lengths[tid];
    idx[tid] = tid;
    __syncthreads();
    for (int k = 2; k <= 256; k <<= 1)
        for (int j = k >> 1; j > 0; j >>= 1) {
            int ixj = tid ^ j;
            if (ixj > tid) {
                bool asc = ((tid & k) == 0);
                int a = key[tid], c = key[ixj];
                bool gt = a > c;
                if (asc == gt) {
                    key[tid] = c; key[ixj] = a;
                    int t2 = idx[tid]; idx[tid] = idx[ixj]; idx[ixj] = t2;
                }
            }
            __syncthreads();
        }
    g_perm[tid] = idx[tid];
}

// ----------------- input projection: LN -> Linear -> GELU -> Linear, writes bf16 hi/lo -----------------
__global__ void halt_proj(const float* __restrict__ x, const int* __restrict__ lengths,
                          const float* __restrict__ ln_g, const float* __restrict__ ln_b,
                          const float* __restrict__ w1, const float* __restrict__ b1,
                          const float* __restrict__ w2, const float* __restrict__ b2) {
    int token = blockIdx.x;
    int b = token >> 9, t = token & 511;
    if (t >= lengths[b]) return;
    __shared__ float sx[25], sn[25], sh1[128];
    int tid = threadIdx.x;
    if (tid < 25) sx[tid] = x[(size_t)token*25 + tid];
    __syncthreads();
    float mu = 0.f;
#pragma unroll
    for (int i = 0; i < 25; i++) mu += sx[i];
    mu *= (1.0f/25.0f);
    float var = 0.f;
#pragma unroll
    for (int i = 0; i < 25; i++) { float d = sx[i]-mu; var += d*d; }
    var *= (1.0f/25.0f);
    float rstd = rsqrtf(var + 1e-5f);
    if (tid < 25) sn[tid] = (sx[tid]-mu)*rstd*ln_g[tid] + ln_b[tid];
    __syncthreads();
    float a = b1[tid];
#pragma unroll
    for (int i = 0; i < 25; i++) a += sn[i]*w1[i*128 + tid];
    float ge = 0.5f*a*(1.0f + erff(a*0.70710678118654752440f));
    sh1[tid] = ge;
    __syncthreads();
    float o = b2[tid];
#pragma unroll 8
    for (int i = 0; i < 128; i++) o += sh1[i]*__ldg(&w2[i*128 + tid]);
    __nv_bfloat16 hbf = __float2bfloat16(o);
    g_ah[(size_t)token*128 + tid] = hbf;
    g_al[(size_t)token*128 + tid] = __float2bfloat16(o - __bfloat162float(hbf));
}

// ----------------- fp32 -> bf16 hi/lo split (weights; per-layer slots) -----------------
__global__ void halt_cvt(const float* __restrict__ src, __nv_bfloat16* __restrict__ hi,
                         __nv_bfloat16* __restrict__ lo, size_t n) {
    size_t i = (size_t)blockIdx.x*256 + threadIdx.x;
    if (i >= n) return;
    float v = src[i];
    __nv_bfloat16 h = __float2bfloat16(v);
    hi[i] = h;
    lo[i] = __float2bfloat16(v - __bfloat162float(h));
}

// ----------------- mma.sync GEMM with cp.async 2-stage pipeline -----------------
__global__ __launch_bounds__(256)
void halt_tcgemm(int K, const __nv_bfloat16* __restrict__ wh, const __nv_bfloat16* __restrict__ wl,
                 const float* __restrict__ bias, const int* __restrict__ lengths) {
    int m0 = blockIdx.x * 128;
    int n0 = blockIdx.y * 128;
    if ((m0 & 511) >= lengths[m0 >> 9]) return;   // fully-padded tile: outputs never read
    extern __shared__ char smem[];
    uint32_t sb = smem_u32(smem);
    int tid = threadIdx.x, warp = tid >> 5, lane = tid & 31;
    int wm = warp & 3, wn = warp >> 2;             // 4 x 2 warp grid, tile 32x64

    if (tid < 128) ((float*)(smem + OFF_BIAS))[tid] = bias[n0 + tid];

    const char* pAh = (const char*)g_ah;
    const char* pAl = (const char*)g_al;
    const char* pBh = (const char*)wh;
    const char* pBl = (const char*)wl;

    float acc[2][8][4];
#pragma unroll
    for (int mi = 0; mi < 2; mi++)
#pragma unroll
        for (int ni = 0; ni < 8; ni++)
#pragma unroll
            for (int q = 0; q < 4; q++) acc[mi][ni][q] = 0.f;

    int arow = wm*32 + (lane & 15);
    int acolsel = (lane >> 4) * 8;
    int brow = wn*64 + (lane & 7) + ((lane & 16) ? 8 : 0);
    int bcolsel = (lane & 8) ? 8 : 0;

    int nchunks = K >> 6;
    auto stage = [&](int c, int buf) {
        uint32_t base = sb + buf*TCG_STAGE;
        for (int it = tid; it < 1024; it += 256) {
            int r = it >> 3, u = it & 7;
            uint32_t sw = SWIZ128((uint32_t)(r*128 + u*16));
            size_t ga = ((size_t)(m0 + r)*K + c*64)*2 + u*16;
            size_t gb = ((size_t)(n0 + r)*K + c*64)*2 + u*16;
            cp16(base + 0     + sw, pAh + ga);
            cp16(base + 16384 + sw, pAl + ga);
            cp16(base + 32768 + sw, pBh + gb);
            cp16(base + 49152 + sw, pBl + gb);
        }
        asm volatile("cp.async.commit_group;" ::: "memory");
    };

    stage(0, 0);
    for (int c = 0; c < nchunks; c++) {
        int buf = c & 1;
        if (c + 1 < nchunks) {
            stage(c + 1, buf ^ 1);
            asm volatile("cp.async.wait_group 1;" ::: "memory");
        } else {
            asm volatile("cp.async.wait_group 0;" ::: "memory");
        }
        __syncthreads();
        uint32_t base = sb + buf*TCG_STAGE;
#pragma unroll
        for (int ks = 0; ks < 4; ks++) {
            int kc = ks*16;
            uint32_t ah[2][4], al[2][4];
#pragma unroll
            for (int mi = 0; mi < 2; mi++) {
                uint32_t off = SWIZ128((uint32_t)((arow + mi*16)*128 + (kc + acolsel)*2));
                ldsm4(ah[mi], base + 0     + off);
                ldsm4(al[mi], base + 16384 + off);
            }
            uint32_t bh[4][4], bl[4][4];
#pragma unroll
            for (int p = 0; p < 4; p++) {
                uint32_t off = SWIZ128((uint32_t)((brow + p*16)*128 + (kc + bcolsel)*2));
                ldsm4(bh[p], base + 32768 + off);
                ldsm4(bl[p], base + 49152 + off);
            }
#pragma unroll
            for (int mi = 0; mi < 2; mi++)
#pragma unroll
                for (int p = 0; p < 4; p++) {
                    mma16816(acc[mi][2*p],   ah[mi], &bh[p][0]);
                    mma16816(acc[mi][2*p],   ah[mi], &bl[p][0]);
                    mma16816(acc[mi][2*p],   al[mi], &bh[p][0]);
                    mma16816(acc[mi][2*p+1], ah[mi], &bh[p][2]);
                    mma16816(acc[mi][2*p+1], ah[mi], &bl[p][2]);
                    mma16816(acc[mi][2*p+1], al[mi], &bh[p][2]);
                }
        }
        __syncthreads();
    }

    const float* sbias = (const float*)(smem + OFF_BIAS);
#pragma unroll
    for (int mi = 0; mi < 2; mi++) {
        int rw = m0 + wm*32 + mi*16 + (lane >> 2);
#pragma unroll
        for (int ni = 0; ni < 8; ni++) {
            int cw = wn*64 + ni*8 + (lane & 3)*2;
            float bx = sbias[cw], by = sbias[cw + 1];
            float2 v0 = { acc[mi][ni][0] + bx, acc[mi][ni][1] + by };
            float2 v1 = { acc[mi][ni][2] + bx, acc[mi][ni][3] + by };
            *(float2*)&g_xw[(size_t)rw*1536 + n0 + cw]       = v0;
            *(float2*)&g_xw[(size_t)(rw + 8)*1536 + n0 + cw] = v1;
        }
    }
}

// ----------------- GRU v6: gate-aligned fragments + register gates, barrier.cluster sync --------
// 128 blocks = 2 dir x 8 bt x 8 hc(32 j); cluster = 8 hc blocks of one (dir,bt).
// Warp: wm=warp>>2 (sample half, m16), wn=warp&3 (8 j cols); 3 gate n8-tiles share (sample,j).
__global__ __launch_bounds__(256, 1) __cluster_dims__(8, 1, 1)
void halt_gru3(const float* __restrict__ xw, float* __restrict__ y,
               const float* __restrict__ Whh, const float* __restrict__ bhh,
               const int* __restrict__ lengths, int last) {
    extern __shared__ char smg[];
    uint32_t sb = smem_u32(smg);
    int grp = blockIdx.x >> 3;
    int hc  = blockIdx.x & 7;
    int dir = grp >> 3;
    int bt  = grp & 7;
    int j0  = hc * 32;
    int tid = threadIdx.x;
    int warp = tid >> 5, lane = tid & 31;
    int wm = warp >> 2, wn = warp & 3;

    // load Whh slice -> smem bf16 hi/lo, [4 chunks][96 rows][64], SW128
    const float* Wd = Whh + (size_t)dir*768*256;
    for (int idx = tid; idx < 96*256; idx += 256) {
        int r = idx >> 8, k = idx & 255;
        int g = r >> 5, jl = r & 31;
        float w = Wd[(size_t)(g*256 + j0 + jl)*256 + k];
        __nv_bfloat16 h = __float2bfloat16(w);
        __nv_bfloat16 l = __float2bfloat16(w - __bfloat162float(h));
        int chunk = k >> 6;
        uint32_t sw = SWIZ128((uint32_t)(r*128 + (k & 63)*2));
        *(__nv_bfloat16*)(smg + OFF_WH + chunk*16384 + sw) = h;
        *(__nv_bfloat16*)(smg + OFF_WL + chunk*16384 + sw) = l;
    }
    __syncthreads();

    // element mapping: thread owns (s_a, jc), (s_a, jc+1), (s_b, jc), (s_b, jc+1)
    int sa = wm*16 + (lane >> 2);          // local sample row (s_b = sa+8)
    int jc = wn*8 + (lane & 3)*2;          // local j col (pair jc, jc+1)
    int jcg = j0 + jc;                     // global j within dir's 256
    float bhr0 = bhh[dir*768 +       jcg], bhr1 = bhh[dir*768 +       jcg + 1];
    float bhz0 = bhh[dir*768 + 256 + jcg], bhz1 = bhh[dir*768 + 256 + jcg + 1];
    float bhn0 = bhh[dir*768 + 512 + jcg], bhn1 = bhh[dir*768 + 512 + jcg + 1];
    int pb2[2], lenv2[2];
#pragma unroll
    for (int si = 0; si < 2; si++) {
        pb2[si]   = g_perm[bt*32 + sa + si*8];
        lenv2[si] = lengths[pb2[si]];
    }
    int tmax = lengths[g_perm[bt*32]];     // sorted desc -> same across cluster

    // cache static B-hi weight fragments in regs: [16 k16][3 gates][2]
    int lx = lane & 15;
    int brx = lx & 7, bsel = (lx & 8) ? 8 : 0;
    uint32_t Bh[16][6];
#pragma unroll
    for (int k16 = 0; k16 < 16; k16++) {
        int chunk = k16 >> 2, kc = (k16 & 3)*16;
#pragma unroll
        for (int g = 0; g < 3; g++) {
            uint32_t off = SWIZ128((uint32_t)((g*32 + wn*8 + brx)*128 + (kc + bsel)*2));
            ldsm2(&Bh[k16][g*2], sb + OFF_WH + chunk*16384 + off);
        }
    }

    int arow = wm*16 + (lane & 15);
    int acolsel = (lane >> 4) * 8;
    int jchunk = jcg >> 6;

    float hprev[4] = {0.f, 0.f, 0.f, 0.f};

    // xw prefetch (one step ahead)
    float2 xr[2], xz[2], xn[2];
    int tok[2];
    auto pref = [&](int tt, float2* pr, float2* pz, float2* pn, int* tk) {
#pragma unroll
        for (int si = 0; si < 2; si++) {
            tk[si] = 0;
            if (tt < lenv2[si]) {
                tk[si] = dir ? (lenv2[si] - 1 - tt) : tt;
                const float* xq = xw + ((size_t)pb2[si]*512 + tk[si])*1536 + dir*768 + jcg;
                pr[si] = *(const float2*)xq;
                pz[si] = *(const float2*)(xq + 256);
                pn[si] = *(const float2*)(xq + 512);
            }
        }
    };
    pref(0, xr, xz, xn, tok);

    for (int t = 0; t < tmax; t++) {
        // phase 1: copy peer-written A tiles (already swizzled layout)
        size_t tb = ((size_t)((t & 1)*2 + dir)*8 + bt) * 16384;
        const uint4* srch = (const uint4*)((const char*)g_hxh + tb);
        const uint4* srcl = (const uint4*)((const char*)g_hxl + tb);
#pragma unroll
        for (int q = 0; q < 4; q++) {
            int it = tid + q*256;
            uint4 vh = __ldcg(&srch[it]);
            uint4 vl = __ldcg(&srcl[it]);
            *(uint4*)(smg + OFF_AH2 + it*16) = vh;
            *(uint4*)(smg + OFF_AL2 + it*16) = vl;
        }
        __syncthreads();

        // phase 2: mma — A ldsm + B-lo ldsm2, B-hi from registers; gate-aligned acc
        float acc[3][4];
#pragma unroll
        for (int g = 0; g < 3; g++) { acc[g][0]=0.f; acc[g][1]=0.f; acc[g][2]=0.f; acc[g][3]=0.f; }
#pragma unroll
        for (int k16 = 0; k16 < 16; k16++) {
            int chunk = k16 >> 2, kc = (k16 & 3)*16;
            uint32_t asw = SWIZ128((uint32_t)(arow*128 + (kc + acolsel)*2));
            uint32_t ah[4], al[4];
            ldsm4(ah, sb + OFF_AH2 + chunk*4096 + asw);
            ldsm4(al, sb + OFF_AL2 + chunk*4096 + asw);
            uint32_t bl[6];
#pragma unroll
            for (int g = 0; g < 3; g++) {
                uint32_t off = SWIZ128((uint32_t)((g*32 + wn*8 + brx)*128 + (kc + bsel)*2));
                ldsm2(&bl[g*2], sb + OFF_WL + chunk*16384 + off);
            }
#pragma unroll
            for (int g = 0; g < 3; g++) {
                mma16816(acc[g], ah, &Bh[k16][g*2]);
                mma16816(acc[g], ah, &bl[g*2]);
                mma16816(acc[g], al, &Bh[k16][g*2]);
            }
        }

        // prefetch xw for NEXT step (lands during barrier + next phases)
        float2 nr[2], nz[2], nn2[2];
        int ntok[2];
        pref(t + 1, nr, nz, nn2, ntok);

        // phase 3: gates in registers; update hprev; store exchange + next-layer A (or y)
        size_t tbn = ((size_t)(((t+1) & 1)*2 + dir)*8 + bt) * 16384;
#pragma unroll
        for (int si = 0; si < 2; si++) {
            if (t < lenv2[si]) {
                int e = si*2;
                int s = sa + si*8;
                float r0 = fsig(xr[si].x + acc[0][e]   + bhr0);
                float r1 = fsig(xr[si].y + acc[0][e+1] + bhr1);
                float z0 = fsig(xz[si].x + acc[1][e]   + bhz0);
                float z1 = fsig(xz[si].y + acc[1][e+1] + bhz1);
                float n0 = ftanh(xn[si].x + r0*(acc[2][e]   + bhn0));
                float n1 = ftanh(xn[si].y + r1*(acc[2][e+1] + bhn1));
                float h0 = (1.f - z0)*n0 + z0*hprev[e];
                float h1 = (1.f - z1)*n1 + z1*hprev[e+1];
                hprev[e] = h0; hprev[e+1] = h1;
                __nv_bfloat16 hb0 = __float2bfloat16(h0);
                __nv_bfloat16 hb1 = __float2bfloat16(h1);
                __nv_bfloat16 lb0 = __float2bfloat16(h0 - __bfloat162float(hb0));
                __nv_bfloat16 lb1 = __float2bfloat16(h1 - __bfloat162float(hb1));
                uint32_t hp = (uint32_t)__bfloat16_as_ushort(hb0) | ((uint32_t)__bfloat16_as_ushort(hb1) << 16);
                uint32_t lp = (uint32_t)__bfloat16_as_ushort(lb0) | ((uint32_t)__bfloat16_as_ushort(lb1) << 16);
                uint32_t sw = SWIZ128((uint32_t)(s*128 + (jcg & 63)*2));
                *(uint32_t*)((char*)g_hxh + tbn + jchunk*4096 + sw) = hp;
                *(uint32_t*)((char*)g_hxl + tbn + jchunk*4096 + sw) = lp;
                size_t oc = ((size_t)pb2[si]*512 + tok[si])*512 + dir*256 + jcg;
                if (last) {
                    *(float2*)&y[oc] = make_float2(h0, h1);
                } else {
                    *(uint32_t*)&g_ah[oc] = hp;
                    *(uint32_t*)&g_al[oc] = lp;
                }
            }
        }
        // cluster barrier: release our h stores, acquire peers' (HW-optimized path)
        asm volatile("barrier.cluster.arrive.aligned;" ::: "memory");
        asm volatile("barrier.cluster.wait.aligned;"   ::: "memory");
#pragma unroll
        for (int si = 0; si < 2; si++) {
            xr[si] = nr[si]; xz[si] = nz[si]; xn[si] = nn2[si]; tok[si] = ntok[si];
        }
    }
}

// ----------------- top-k pooling + classifier -----------------
__global__ __launch_bounds__(256)
void halt_pool(const float* __restrict__ H, const int* __restrict__ lengths,
               const float* __restrict__ Wc, const float* __restrict__ bc,
               float* __restrict__ out) {
    int b = blockIdx.x, tid = threadIdx.x;
    __shared__ float ns[512];
    __shared__ int   si[512];
    __shared__ float red[256];
    int len = lengths[b];
    int warp = tid >> 5, lane = tid & 31;
    for (int r = warp; r < 512; r += 8) {
        float sc = 1e9f;
        if (r < len) {
            const float* row = H + ((size_t)b*512 + r)*512;
            float acc = 0.f;
#pragma unroll 4
            for (int d = lane; d < 512; d += 32) { float v = row[d]; acc += v*v; }
#pragma unroll
            for (int o = 16; o > 0; o >>= 1) acc += __shfl_xor_sync(0xffffffffu, acc, o);
            sc = -sqrtf(acc);
        }
        if (lane == 0) { ns[r] = sc; si[r] = r; }
    }
    __syncthreads();
    for (int k = 2; k <= 512; k <<= 1)
        for (int j = k >> 1; j > 0; j >>= 1) {
            for (int i = tid; i < 512; i += 256) {
                int ixj = i ^ j;
                if (ixj > i) {
                    bool asc = ((i & k) == 0);
                    float a = ns[i], c = ns[ixj];
                    int ia = si[i], ic = si[ixj];
                    bool gt = (a > c) || (a == c && ia > ic);
                    if (asc == gt) { ns[i] = c; ns[ixj] = a; si[i] = ic; si[ixj] = ia; }
                }
            }
            __syncthreads();
        }
    int kk = (int)ceilf((float)len * 0.15f);
    if (kk < 1) kk = 1;
    float a0 = 0.f, a1 = 0.f;
    for (int i = 0; i < kk; i++) {
        int r = si[i];
        const float* row = H + ((size_t)b*512 + r)*512;
        a0 += row[tid]; a1 += row[tid + 256];
    }
    float kf = (float)kk;
    float part = (a0/kf)*Wc[tid] + (a1/kf)*Wc[tid + 256];
    red[tid] = part;
    __syncthreads();
    for (int s2 = 128; s2 > 0; s2 >>= 1) {
        if (tid < s2) red[tid] += red[tid + s2];
        __syncthreads();
    }
    if (tid == 0) out[b] = red[0] + bc[0];
}

// ----------------- host orchestration -----------------
extern "C" void kernel_launch(void* const* d_in, const int* in_sizes, int n_in,
                              void* d_out, int out_size) {
    const float* x    = (const float*)d_in[0];
    const int*   lens = (const int*)  d_in[1];
    const float* ln_g = (const float*)d_in[2];
    const float* ln_b = (const float*)d_in[3];
    const float* w1   = (const float*)d_in[4];
    const float* b1   = (const float*)d_in[5];
    const float* w2   = (const float*)d_in[6];
    const float* b2   = (const float*)d_in[7];
    const float* Wih0 = (const float*)d_in[8];
    const float* Whh0 = (const float*)d_in[9];
    const float* bih0 = (const float*)d_in[10];
    const float* bhh0 = (const float*)d_in[11];
    const float* Wih  = (const float*)d_in[12];
    const float* Whh  = (const float*)d_in[13];
    const float* bih  = (const float*)d_in[14];
    const float* bhh  = (const float*)d_in[15];
    const float* Wc   = (const float*)d_in[16];
    const float* bc   = (const float*)d_in[17];
    float* out = (float*)d_out;

    cudaFuncSetAttribute(halt_gru3, cudaFuncAttributeMaxDynamicSharedMemorySize, SMEM_G3);
    cudaFuncSetAttribute(halt_tcgemm, cudaFuncAttributeMaxDynamicSharedMemorySize, SMEM_TC);

    void *pB = 0, *pxw = 0, *pwh = 0, *pwl = 0, *phxh = 0, *phxl = 0;
    cudaGetSymbolAddress(&pB,   g_bufB);
    cudaGetSymbolAddress(&pxw,  g_xw);
    cudaGetSymbolAddress(&pwh,  g_wh);
    cudaGetSymbolAddress(&pwl,  g_wl);
    cudaGetSymbolAddress(&phxh, g_hxh);
    cudaGetSymbolAddress(&phxl, g_hxl);
    float* fB  = (float*)pB;
    float* fxw = (float*)pxw;

    halt_sort_perm<<<1, 256>>>(lens);
    halt_proj<<<NT, 128>>>(x, lens, ln_g, ln_b, w1, b1, w2, b2);

    for (int l = 0; l < 5; l++) {
        const float* Wi = l ? (Wih + (size_t)(l-1)*2*768*512) : Wih0;
        int K = l ? 512 : 128;
        size_t nW = (size_t)1536 * K;
        __nv_bfloat16* wh = (__nv_bfloat16*)pwh + (size_t)l*1536*512;
        __nv_bfloat16* wl = (__nv_bfloat16*)pwl + (size_t)l*1536*512;
        halt_cvt<<<(unsigned)((nW + 255)/256), 256>>>(Wi, wh, wl, nW);
    }

    for (int l = 0; l < 5; l++) {
        const float* bi = l ? (bih + (l-1)*1536) : bih0;
        const float* Wh = l ? (Whh + (size_t)(l-1)*2*768*256) : Whh0;
        const float* bh = l ? (bhh + (l-1)*1536) : bhh0;
        int K = l ? 512 : 128;
        const __nv_bfloat16* wh = (const __nv_bfloat16*)pwh + (size_t)l*1536*512;
        const __nv_bfloat16* wl = (const __nv_bfloat16*)pwl + (size_t)l*1536*512;

        cudaMemsetAsync(phxh, 0, (size_t)2*2*8*4*32*64*sizeof(__nv_bfloat16));
        cudaMemsetAsync(phxl, 0, (size_t)2*2*8*4*32*64*sizeof(__nv_bfloat16));

        dim3 gg(NT/128, 12);
        halt_tcgemm<<<gg, 256, SMEM_TC>>>(K, wh, wl, bi, lens);

        halt_gru3<<<128, 256, SMEM_G3>>>(fxw, fB, Wh, bh, lens, (l == 4) ? 1 : 0);
    }
    halt_pool<<<256, 256>>>(fB, lens, Wc, bc, out);
}

// round 14
// speedup vs baseline: 1.3681x; 1.0916x over previous
#include <cuda_runtime.h>
#include <cuda_bf16.h>
#include <math.h>
#include <stdint.h>

#define Bn   256
#define Tn   512
#define NT   (Bn*Tn)          // 131072 tokens

// tcgemm smem: 2 stages x (A hi/lo 16KB each + B hi/lo 32KB each) + bias
#define TCG_STAGE  98304
#define OFF_BIAS   196608
#define SMEM_TC    (196608 + 1024)

// GRU smem (bytes)
#define OFF_WH   0                    // Whh hi  [4 chunks][96 rows][64] bf16
#define OFF_WL   65536                // Whh lo
#define OFF_AH2  131072               // h hi    [4 chunks][32 rows][64] bf16
#define OFF_AL2  147456               // h lo
#define SMEM_G3  163840

// ----------------- device scratch (bss-zeroed at module load) -----------------
__device__ float g_xw  [(size_t)NT*1536];   // input-gate precompute, reused per layer
__device__ float g_bufB[(size_t)NT*512];    // final-layer fp32 activations (pool input)
__device__ int   g_perm[256];               // batch order sorted by length desc
__device__ __nv_bfloat16 g_ah[(size_t)NT*512];   // A hi split (GEMM input)
__device__ __nv_bfloat16 g_al[(size_t)NT*512];   // A lo split
__device__ __nv_bfloat16 g_wh[5*1536*512];       // W hi split, per-layer slots
__device__ __nv_bfloat16 g_wl[5*1536*512];       // W lo split
// h exchange in A-tile layout: [pp][dir][bt][chunk4][row32][col64] bf16
__device__ __nv_bfloat16 g_hxh[2*2*8*4*32*64];
__device__ __nv_bfloat16 g_hxl[2*2*8*4*32*64];

// ----------------- mma.sync helpers (base ISA, compiles at compute_103) -----------------
__device__ __forceinline__ uint32_t smem_u32(const void* p) {
    uint32_t a;
    asm("{ .reg .u64 t; cvta.to.shared.u64 t, %1; cvt.u32.u64 %0, t; }" : "=r"(a) : "l"(p));
    return a;
}
#define SWIZ128(b) ((b) ^ (((b) >> 3) & 0x70))

__device__ __forceinline__ void ldsm4(uint32_t* r, uint32_t addr) {
    asm volatile("ldmatrix.sync.aligned.m8n8.x4.shared.b16 {%0,%1,%2,%3}, [%4];"
                 : "=r"(r[0]), "=r"(r[1]), "=r"(r[2]), "=r"(r[3]) : "r"(addr));
}
__device__ __forceinline__ void ldsm2(uint32_t* r, uint32_t addr) {
    asm volatile("ldmatrix.sync.aligned.m8n8.x2.shared.b16 {%0,%1}, [%2];"
                 : "=r"(r[0]), "=r"(r[1]) : "r"(addr));
}
__device__ __forceinline__ void mma16816(float* c, const uint32_t* a, const uint32_t* b) {
    asm volatile("mma.sync.aligned.m16n8k16.row.col.f32.bf16.bf16.f32 "
                 "{%0,%1,%2,%3}, {%4,%5,%6,%7}, {%8,%9}, {%0,%1,%2,%3};"
                 : "+f"(c[0]), "+f"(c[1]), "+f"(c[2]), "+f"(c[3])
                 : "r"(a[0]), "r"(a[1]), "r"(a[2]), "r"(a[3]), "r"(b[0]), "r"(b[1]));
}
__device__ __forceinline__ void cp16(uint32_t dst, const void* src) {
    asm volatile("cp.async.cg.shared.global [%0], [%1], 16;" :: "r"(dst), "l"(src) : "memory");
}

// fast gates: MUFU-based sigmoid/tanh (err ~1e-6, saturates correctly)
__device__ __forceinline__ float fsig(float x) {
    return __fdividef(1.f, 1.f + __expf(-x));
}
__device__ __forceinline__ float ftanh(float x) {
    return __fdividef(2.f, 1.f + __expf(-2.f*x)) - 1.f;
}

// ----------------- sort batch indices by length descending -----------------
__global__ void halt_sort_perm(const int* __restrict__ lengths) {
    __shared__ int key[256];
    __shared__ int idx[256];
    int tid = threadIdx.x;
    key[tid] = -lengths[tid];
    idx[tid] = tid;
    __syncthreads();
    for (int k = 2; k <= 256; k <<= 1)
        for (int j = k >> 1; j > 0; j >>= 1) {
            int ixj = tid ^ j;
            if (ixj > tid) {
                bool asc = ((tid & k) == 0);
                int a = key[tid], c = key[ixj];
                bool gt = a > c;
                if (asc == gt) {
                    key[tid] = c; key[ixj] = a;
                    int t2 = idx[tid]; idx[tid] = idx[ixj]; idx[ixj] = t2;
                }
            }
            __syncthreads();
        }
    g_perm[tid] = idx[tid];
}

// ----------------- input projection: LN -> Linear -> GELU -> Linear, writes bf16 hi/lo -----------------
__global__ void halt_proj(const float* __restrict__ x, const int* __restrict__ lengths,
                          const float* __restrict__ ln_g, const float* __restrict__ ln_b,
                          const float* __restrict__ w1, const float* __restrict__ b1,
                          const float* __restrict__ w2, const float* __restrict__ b2) {
    int token = blockIdx.x;
    int b = token >> 9, t = token & 511;
    if (t >= lengths[b]) return;
    __shared__ float sx[25], sn[25], sh1[128];
    int tid = threadIdx.x;
    if (tid < 25) sx[tid] = x[(size_t)token*25 + tid];
    __syncthreads();
    float mu = 0.f;
#pragma unroll
    for (int i = 0; i < 25; i++) mu += sx[i];
    mu *= (1.0f/25.0f);
    float var = 0.f;
#pragma unroll
    for (int i = 0; i < 25; i++) { float d = sx[i]-mu; var += d*d; }
    var *= (1.0f/25.0f);
    float rstd = rsqrtf(var + 1e-5f);
    if (tid < 25) sn[tid] = (sx[tid]-mu)*rstd*ln_g[tid] + ln_b[tid];
    __syncthreads();
    float a = b1[tid];
#pragma unroll
    for (int i = 0; i < 25; i++) a += sn[i]*w1[i*128 + tid];
    float ge = 0.5f*a*(1.0f + erff(a*0.70710678118654752440f));
    sh1[tid] = ge;
    __syncthreads();
    float o = b2[tid];
#pragma unroll 8
    for (int i = 0; i < 128; i++) o += sh1[i]*__ldg(&w2[i*128 + tid]);
    __nv_bfloat16 hbf = __float2bfloat16(o);
    g_ah[(size_t)token*128 + tid] = hbf;
    g_al[(size_t)token*128 + tid] = __float2bfloat16(o - __bfloat162float(hbf));
}

// ----------------- fp32 -> bf16 hi/lo split (weights; per-layer slots) -----------------
__global__ void halt_cvt(const float* __restrict__ src, __nv_bfloat16* __restrict__ hi,
                         __nv_bfloat16* __restrict__ lo, size_t n) {
    size_t i = (size_t)blockIdx.x*256 + threadIdx.x;
    if (i >= n) return;
    float v = src[i];
    __nv_bfloat16 h = __float2bfloat16(v);
    hi[i] = h;
    lo[i] = __float2bfloat16(v - __bfloat162float(h));
}

// ----------------- mma.sync GEMM, n-tile 256, cp.async 2-stage pipeline -----------------
__global__ __launch_bounds__(256)
void halt_tcgemm(int K, const __nv_bfloat16* __restrict__ wh, const __nv_bfloat16* __restrict__ wl,
                 const float* __restrict__ bias, const int* __restrict__ lengths) {
    int m0 = blockIdx.x * 128;
    int n0 = blockIdx.y * 256;
    if ((m0 & 511) >= lengths[m0 >> 9]) return;   // fully-padded tile: outputs never read
    extern __shared__ char smem[];
    uint32_t sb = smem_u32(smem);
    int tid = threadIdx.x, warp = tid >> 5, lane = tid & 31;
    int wm = warp & 3, wn = warp >> 2;             // 4 x 2 warp grid, warp tile 32m x 128n

    ((float*)(smem + OFF_BIAS))[tid] = bias[n0 + tid];

    const char* pAh = (const char*)g_ah;
    const char* pAl = (const char*)g_al;
    const char* pBh = (const char*)wh;
    const char* pBl = (const char*)wl;

    float acc[2][16][4];
#pragma unroll
    for (int mi = 0; mi < 2; mi++)
#pragma unroll
        for (int ni = 0; ni < 16; ni++)
#pragma unroll
            for (int q = 0; q < 4; q++) acc[mi][ni][q] = 0.f;

    int arow = wm*32 + (lane & 15);
    int acolsel = (lane >> 4) * 8;
    int brow = wn*128 + (lane & 7) + ((lane & 16) ? 8 : 0);
    int bcolsel = (lane & 8) ? 8 : 0;

    int nchunks = K >> 6;
    auto stage = [&](int c, int buf) {
        uint32_t base = sb + buf*TCG_STAGE;
        for (int it = tid; it < 1024; it += 256) {
            int r = it >> 3, u = it & 7;
            uint32_t sw = SWIZ128((uint32_t)(r*128 + u*16));
            size_t ga = ((size_t)(m0 + r)*K + c*64)*2 + u*16;
            cp16(base + 0     + sw, pAh + ga);
            cp16(base + 16384 + sw, pAl + ga);
        }
        for (int it = tid; it < 2048; it += 256) {
            int r = it >> 3, u = it & 7;
            uint32_t sw = SWIZ128((uint32_t)(r*128 + u*16));
            size_t gb = ((size_t)(n0 + r)*K + c*64)*2 + u*16;
            cp16(base + 32768 + sw, pBh + gb);
            cp16(base + 65536 + sw, pBl + gb);
        }
        asm volatile("cp.async.commit_group;" ::: "memory");
    };

    stage(0, 0);
    for (int c = 0; c < nchunks; c++) {
        int buf = c & 1;
        if (c + 1 < nchunks) {
            stage(c + 1, buf ^ 1);
            asm volatile("cp.async.wait_group 1;" ::: "memory");
        } else {
            asm volatile("cp.async.wait_group 0;" ::: "memory");
        }
        __syncthreads();
        uint32_t base = sb + buf*TCG_STAGE;
#pragma unroll
        for (int ks = 0; ks < 4; ks++) {
            int kc = ks*16;
            uint32_t ah[2][4], al[2][4];
#pragma unroll
            for (int mi = 0; mi < 2; mi++) {
                uint32_t off = SWIZ128((uint32_t)((arow + mi*16)*128 + (kc + acolsel)*2));
                ldsm4(ah[mi], base + 0     + off);
                ldsm4(al[mi], base + 16384 + off);
            }
            // p-halves limit live B fragments (register pressure)
#pragma unroll
            for (int ph = 0; ph < 2; ph++) {
                uint32_t bh[4][4], bl[4][4];
#pragma unroll
                for (int p = 0; p < 4; p++) {
                    int pp = ph*4 + p;
                    uint32_t off = SWIZ128((uint32_t)((brow + pp*16)*128 + (kc + bcolsel)*2));
                    ldsm4(bh[p], base + 32768 + off);
                    ldsm4(bl[p], base + 65536 + off);
                }
#pragma unroll
                for (int mi = 0; mi < 2; mi++)
#pragma unroll
                    for (int p = 0; p < 4; p++) {
                        int ni = ph*8 + 2*p;
                        mma16816(acc[mi][ni],   ah[mi], &bh[p][0]);
                        mma16816(acc[mi][ni],   ah[mi], &bl[p][0]);
                        mma16816(acc[mi][ni],   al[mi], &bh[p][0]);
                        mma16816(acc[mi][ni+1], ah[mi], &bh[p][2]);
                        mma16816(acc[mi][ni+1], ah[mi], &bl[p][2]);
                        mma16816(acc[mi][ni+1], al[mi], &bh[p][2]);
                    }
            }
        }
        __syncthreads();
    }

    const float* sbias = (const float*)(smem + OFF_BIAS);
#pragma unroll
    for (int mi = 0; mi < 2; mi++) {
        int rw = m0 + wm*32 + mi*16 + (lane >> 2);
#pragma unroll
        for (int ni = 0; ni < 16; ni++) {
            int cw = wn*128 + ni*8 + (lane & 3)*2;
            float bx = sbias[cw], by = sbias[cw + 1];
            float2 v0 = { acc[mi][ni][0] + bx, acc[mi][ni][1] + by };
            float2 v1 = { acc[mi][ni][2] + bx, acc[mi][ni][3] + by };
            *(float2*)&g_xw[(size_t)rw*1536 + n0 + cw]       = v0;
            *(float2*)&g_xw[(size_t)(rw + 8)*1536 + n0 + cw] = v1;
        }
    }
}

// ----------------- GRU v7: split cluster barrier, cp.async exchange, merged B-lo loads ----------
// 128 blocks = 2 dir x 8 bt x 8 hc(32 j); cluster = 8 hc blocks of one (dir,bt).
__global__ __launch_bounds__(256, 1) __cluster_dims__(8, 1, 1)
void halt_gru3(const float* __restrict__ xw, float* __restrict__ y,
               const float* __restrict__ Whh, const float* __restrict__ bhh,
               const int* __restrict__ lengths, int last) {
    extern __shared__ char smg[];
    uint32_t sb = smem_u32(smg);
    int grp = blockIdx.x >> 3;
    int hc  = blockIdx.x & 7;
    int dir = grp >> 3;
    int bt  = grp & 7;
    int j0  = hc * 32;
    int tid = threadIdx.x;
    int warp = tid >> 5, lane = tid & 31;
    int wm = warp >> 2, wn = warp & 3;

    // load Whh slice -> smem bf16 hi/lo, [4 chunks][96 rows][64], SW128
    const float* Wd = Whh + (size_t)dir*768*256;
    for (int idx = tid; idx < 96*256; idx += 256) {
        int r = idx >> 8, k = idx & 255;
        int g = r >> 5, jl = r & 31;
        float w = Wd[(size_t)(g*256 + j0 + jl)*256 + k];
        __nv_bfloat16 h = __float2bfloat16(w);
        __nv_bfloat16 l = __float2bfloat16(w - __bfloat162float(h));
        int chunk = k >> 6;
        uint32_t sw = SWIZ128((uint32_t)(r*128 + (k & 63)*2));
        *(__nv_bfloat16*)(smg + OFF_WH + chunk*16384 + sw) = h;
        *(__nv_bfloat16*)(smg + OFF_WL + chunk*16384 + sw) = l;
    }
    __syncthreads();

    // element mapping: thread owns (s_a, jc..jc+1), (s_a+8, jc..jc+1)
    int sa = wm*16 + (lane >> 2);
    int jc = wn*8 + (lane & 3)*2;
    int jcg = j0 + jc;
    float bhr0 = bhh[dir*768 +       jcg], bhr1 = bhh[dir*768 +       jcg + 1];
    float bhz0 = bhh[dir*768 + 256 + jcg], bhz1 = bhh[dir*768 + 256 + jcg + 1];
    float bhn0 = bhh[dir*768 + 512 + jcg], bhn1 = bhh[dir*768 + 512 + jcg + 1];
    int pb2[2], lenv2[2];
#pragma unroll
    for (int si = 0; si < 2; si++) {
        pb2[si]   = g_perm[bt*32 + sa + si*8];
        lenv2[si] = lengths[pb2[si]];
    }
    int tmax = lengths[g_perm[bt*32]];     // sorted desc -> same across cluster

    // merged B fragment addressing: ldsm4 (gates 0,1) per-lane matrix = lane>>3,
    // g = m>>1, k-half = (m&1)*8; ldsm2 (gate 2) lanes 0-15.
    int m4 = lane >> 3;
    int g4 = m4 >> 1, kh4 = (m4 & 1) * 8;
    int row4 = g4*32 + wn*8 + (lane & 7);
    int lx = lane & 15;
    int brx = lx & 7, bsel = (lx & 8) ? 8 : 0;
    int row2 = 64 + wn*8 + brx;

    // cache static B-hi weight fragments in regs: [16 k16][3 gates][2]
    uint32_t Bh[16][6];
#pragma unroll
    for (int k16 = 0; k16 < 16; k16++) {
        int chunk = k16 >> 2, kc = (k16 & 3)*16;
        uint32_t off4 = SWIZ128((uint32_t)(row4*128 + (kc + kh4)*2));
        ldsm4(&Bh[k16][0], sb + OFF_WH + chunk*16384 + off4);
        uint32_t off2 = SWIZ128((uint32_t)(row2*128 + (kc + bsel)*2));
        ldsm2(&Bh[k16][4], sb + OFF_WH + chunk*16384 + off2);
    }

    int arow = wm*16 + (lane & 15);
    int acolsel = (lane >> 4) * 8;
    int jchunk = jcg >> 6;

    float hprev[4] = {0.f, 0.f, 0.f, 0.f};

    // xw prefetch (one step ahead)
    float2 xr[2], xz[2], xn[2];
    int tok[2];
    auto pref = [&](int tt, float2* pr, float2* pz, float2* pn, int* tk) {
#pragma unroll
        for (int si = 0; si < 2; si++) {
            tk[si] = 0;
            if (tt < lenv2[si]) {
                tk[si] = dir ? (lenv2[si] - 1 - tt) : tt;
                const float* xq = xw + ((size_t)pb2[si]*512 + tk[si])*1536 + dir*768 + jcg;
                pr[si] = *(const float2*)xq;
                pz[si] = *(const float2*)(xq + 256);
                pn[si] = *(const float2*)(xq + 512);
            }
        }
    };
    pref(0, xr, xz, xn, tok);

    for (int t = 0; t < tmax; t++) {
        // phase 1: cp.async copy of peer-written A tiles (already swizzled layout)
        size_t tb = ((size_t)((t & 1)*2 + dir)*8 + bt) * 16384;
        const char* srch = (const char*)g_hxh + tb;
        const char* srcl = (const char*)g_hxl + tb;
#pragma unroll
        for (int q = 0; q < 4; q++) {
            int it = (tid + q*256) * 16;
            cp16(sb + OFF_AH2 + it, srch + it);
            cp16(sb + OFF_AL2 + it, srcl + it);
        }
        asm volatile("cp.async.commit_group;" ::: "memory");
        asm volatile("cp.async.wait_group 0;" ::: "memory");
        __syncthreads();

        // phase 2: mma — A ldsm + B-lo (ldsm4+ldsm2), B-hi from registers; gate-aligned acc
        float acc[3][4];
#pragma unroll
        for (int g = 0; g < 3; g++) { acc[g][0]=0.f; acc[g][1]=0.f; acc[g][2]=0.f; acc[g][3]=0.f; }
#pragma unroll
        for (int k16 = 0; k16 < 16; k16++) {
            int chunk = k16 >> 2, kc = (k16 & 3)*16;
            uint32_t asw = SWIZ128((uint32_t)(arow*128 + (kc + acolsel)*2));
            uint32_t ah[4], al[4];
            ldsm4(ah, sb + OFF_AH2 + chunk*4096 + asw);
            ldsm4(al, sb + OFF_AL2 + chunk*4096 + asw);
            uint32_t bl[6];
            uint32_t off4 = SWIZ128((uint32_t)(row4*128 + (kc + kh4)*2));
            ldsm4(&bl[0], sb + OFF_WL + chunk*16384 + off4);
            uint32_t off2 = SWIZ128((uint32_t)(row2*128 + (kc + bsel)*2));
            ldsm2(&bl[4], sb + OFF_WL + chunk*16384 + off2);
#pragma unroll
            for (int g = 0; g < 3; g++) {
                mma16816(acc[g], ah, &Bh[k16][g*2]);
                mma16816(acc[g], ah, &bl[g*2]);
                mma16816(acc[g], al, &Bh[k16][g*2]);
            }
        }

        // prefetch xw for NEXT step (lands during barrier + next phases)
        float2 nr[2], nz[2], nn2[2];
        int ntok[2];
        pref(t + 1, nr, nz, nn2, ntok);

        // phase 3a: gates; update hprev; store peer-consumed h exchange tiles
        size_t tbn = ((size_t)(((t+1) & 1)*2 + dir)*8 + bt) * 16384;
        uint32_t hpv[2], lpv[2];
#pragma unroll
        for (int si = 0; si < 2; si++) {
            if (t < lenv2[si]) {
                int e = si*2;
                int s = sa + si*8;
                float r0 = fsig(xr[si].x + acc[0][e]   + bhr0);
                float r1 = fsig(xr[si].y + acc[0][e+1] + bhr1);
                float z0 = fsig(xz[si].x + acc[1][e]   + bhz0);
                float z1 = fsig(xz[si].y + acc[1][e+1] + bhz1);
                float n0 = ftanh(xn[si].x + r0*(acc[2][e]   + bhn0));
                float n1 = ftanh(xn[si].y + r1*(acc[2][e+1] + bhn1));
                float h0 = (1.f - z0)*n0 + z0*hprev[e];
                float h1 = (1.f - z1)*n1 + z1*hprev[e+1];
                hprev[e] = h0; hprev[e+1] = h1;
                __nv_bfloat16 hb0 = __float2bfloat16(h0);
                __nv_bfloat16 hb1 = __float2bfloat16(h1);
                __nv_bfloat16 lb0 = __float2bfloat16(h0 - __bfloat162float(hb0));
                __nv_bfloat16 lb1 = __float2bfloat16(h1 - __bfloat162float(hb1));
                hpv[si] = (uint32_t)__bfloat16_as_ushort(hb0) | ((uint32_t)__bfloat16_as_ushort(hb1) << 16);
                lpv[si] = (uint32_t)__bfloat16_as_ushort(lb0) | ((uint32_t)__bfloat16_as_ushort(lb1) << 16);
                uint32_t sw = SWIZ128((uint32_t)(s*128 + (jcg & 63)*2));
                *(uint32_t*)((char*)g_hxh + tbn + jchunk*4096 + sw) = hpv[si];
                *(uint32_t*)((char*)g_hxl + tbn + jchunk*4096 + sw) = lpv[si];
            }
        }
        // arrive early (releases our exchange stores), overlap non-peer work, then wait
        asm volatile("barrier.cluster.arrive.aligned;" ::: "memory");
#pragma unroll
        for (int si = 0; si < 2; si++) {
            if (t < lenv2[si]) {
                size_t oc = ((size_t)pb2[si]*512 + tok[si])*512 + dir*256 + jcg;
                if (last) {
                    float2 hv;
                    hv.x = __bfloat162float(__ushort_as_bfloat16((unsigned short)(hpv[si] & 0xffff)))
                         + __bfloat162float(__ushort_as_bfloat16((unsigned short)(lpv[si] & 0xffff)));
                    hv.y = __bfloat162float(__ushort_as_bfloat16((unsigned short)(hpv[si] >> 16)))
                         + __bfloat162float(__ushort_as_bfloat16((unsigned short)(lpv[si] >> 16)));
                    *(float2*)&y[oc] = hv;
                } else {
                    *(uint32_t*)&g_ah[oc] = hpv[si];
                    *(uint32_t*)&g_al[oc] = lpv[si];
                }
            }
            xr[si] = nr[si]; xz[si] = nz[si]; xn[si] = nn2[si]; tok[si] = ntok[si];
        }
        asm volatile("barrier.cluster.wait.aligned;" ::: "memory");
    }
}

// ----------------- top-k pooling + classifier -----------------
__global__ __launch_bounds__(256)
void halt_pool(const float* __restrict__ H, const int* __restrict__ lengths,
               const float* __restrict__ Wc, const float* __restrict__ bc,
               float* __restrict__ out) {
    int b = blockIdx.x, tid = threadIdx.x;
    __shared__ float ns[512];
    __shared__ int   si[512];
    __shared__ float red[256];
    int len = lengths[b];
    int warp = tid >> 5, lane = tid & 31;
    for (int r = warp; r < 512; r += 8) {
        float sc = 1e9f;
        if (r < len) {
            const float* row = H + ((size_t)b*512 + r)*512;
            float acc = 0.f;
#pragma unroll 4
            for (int d = lane; d < 512; d += 32) { float v = row[d]; acc += v*v; }
#pragma unroll
            for (int o = 16; o > 0; o >>= 1) acc += __shfl_xor_sync(0xffffffffu, acc, o);
            sc = -sqrtf(acc);
        }
        if (lane == 0) { ns[r] = sc; si[r] = r; }
    }
    __syncthreads();
    for (int k = 2; k <= 512; k <<= 1)
        for (int j = k >> 1; j > 0; j >>= 1) {
            for (int i = tid; i < 512; i += 256) {
                int ixj = i ^ j;
                if (ixj > i) {
                    bool asc = ((i & k) == 0);
                    float a = ns[i], c = ns[ixj];
                    int ia = si[i], ic = si[ixj];
                    bool gt = (a > c) || (a == c && ia > ic);
                    if (asc == gt) { ns[i] = c; ns[ixj] = a; si[i] = ic; si[ixj] = ia; }
                }
            }
            __syncthreads();
        }
    int kk = (int)ceilf((float)len * 0.15f);
    if (kk < 1) kk = 1;
    float a0 = 0.f, a1 = 0.f;
    for (int i = 0; i < kk; i++) {
        int r = si[i];
        const float* row = H + ((size_t)b*512 + r)*512;
        a0 += row[tid]; a1 += row[tid + 256];
    }
    float kf = (float)kk;
    float part = (a0/kf)*Wc[tid] + (a1/kf)*Wc[tid + 256];
    red[tid] = part;
    __syncthreads();
    for (int s2 = 128; s2 > 0; s2 >>= 1) {
        if (tid < s2) red[tid] += red[tid + s2];
        __syncthreads();
    }
    if (tid == 0) out[b] = red[0] + bc[0];
}

// ----------------- host orchestration -----------------
extern "C" void kernel_launch(void* const* d_in, const int* in_sizes, int n_in,
                              void* d_out, int out_size) {
    const float* x    = (const float*)d_in[0];
    const int*   lens = (const int*)  d_in[1];
    const float* ln_g = (const float*)d_in[2];
    const float* ln_b = (const float*)d_in[3];
    const float* w1   = (const float*)d_in[4];
    const float* b1   = (const float*)d_in[5];
    const float* w2   = (const float*)d_in[6];
    const float* b2   = (const float*)d_in[7];
    const float* Wih0 = (const float*)d_in[8];
    const float* Whh0 = (const float*)d_in[9];
    const float* bih0 = (const float*)d_in[10];
    const float* bhh0 = (const float*)d_in[11];
    const float* Wih  = (const float*)d_in[12];
    const float* Whh  = (const float*)d_in[13];
    const float* bih  = (const float*)d_in[14];
    const float* bhh  = (const float*)d_in[15];
    const float* Wc   = (const float*)d_in[16];
    const float* bc   = (const float*)d_in[17];
    float* out = (float*)d_out;

    cudaFuncSetAttribute(halt_gru3, cudaFuncAttributeMaxDynamicSharedMemorySize, SMEM_G3);
    cudaFuncSetAttribute(halt_tcgemm, cudaFuncAttributeMaxDynamicSharedMemorySize, SMEM_TC);

    void *pB = 0, *pxw = 0, *pwh = 0, *pwl = 0, *phxh = 0, *phxl = 0;
    cudaGetSymbolAddress(&pB,   g_bufB);
    cudaGetSymbolAddress(&pxw,  g_xw);
    cudaGetSymbolAddress(&pwh,  g_wh);
    cudaGetSymbolAddress(&pwl,  g_wl);
    cudaGetSymbolAddress(&phxh, g_hxh);
    cudaGetSymbolAddress(&phxl, g_hxl);
    float* fB  = (float*)pB;
    float* fxw = (float*)pxw;

    halt_sort_perm<<<1, 256>>>(lens);
    halt_proj<<<NT, 128>>>(x, lens, ln_g, ln_b, w1, b1, w2, b2);

    for (int l = 0; l < 5; l++) {
        const float* Wi = l ? (Wih + (size_t)(l-1)*2*768*512) : Wih0;
        int K = l ? 512 : 128;
        size_t nW = (size_t)1536 * K;
        __nv_bfloat16* wh = (__nv_bfloat16*)pwh + (size_t)l*1536*512;
        __nv_bfloat16* wl = (__nv_bfloat16*)pwl + (size_t)l*1536*512;
        halt_cvt<<<(unsigned)((nW + 255)/256), 256>>>(Wi, wh, wl, nW);
    }

    for (int l = 0; l < 5; l++) {
        const float* bi = l ? (bih + (l-1)*1536) : bih0;
        const float* Wh = l ? (Whh + (size_t)(l-1)*2*768*256) : Whh0;
        const float* bh = l ? (bhh + (l-1)*1536) : bhh0;
        int K = l ? 512 : 128;
        const __nv_bfloat16* wh = (const __nv_bfloat16*)pwh + (size_t)l*1536*512;
        const __nv_bfloat16* wl = (const __nv_bfloat16*)pwl + (size_t)l*1536*512;

        cudaMemsetAsync(phxh, 0, (size_t)2*2*8*4*32*64*sizeof(__nv_bfloat16));
        cudaMemsetAsync(phxl, 0, (size_t)2*2*8*4*32*64*sizeof(__nv_bfloat16));

        dim3 gg(NT/128, 6);
        halt_tcgemm<<<gg, 256, SMEM_TC>>>(K, wh, wl, bi, lens);

        halt_gru3<<<128, 256, SMEM_G3>>>(fxw, fB, Wh, bh, lens, (l == 4) ? 1 : 0);
    }
    halt_pool<<<256, 256>>>(fB, lens, Wc, bc, out);
}

// round 15
// speedup vs baseline: 1.3836x; 1.0114x over previous
#include <cuda_runtime.h>
#include <cuda_bf16.h>
#include <math.h>
#include <stdint.h>

#define Bn   256
#define Tn   512
#define NT   (Bn*Tn)          // 131072 tokens

// tcgemm smem: 2 stages x (A hi/lo 16KB each + B hi/lo 32KB each) + bias
#define TCG_STAGE  98304
#define OFF_BIAS   196608
#define SMEM_TC    (196608 + 1024)

// GRU smem (bytes)
#define OFF_WH   0                    // Whh hi  [4 chunks][96 rows][64] bf16
#define OFF_WL   65536                // Whh lo
#define OFF_AH2  131072               // h hi    [4 chunks][32 rows][64] bf16
#define OFF_AL2  147456               // h lo
#define OFF_XW   163840               // xw stage: 2 bufs x [32 s][100 floats]
#define OFF_META 189440               // pb[32], len[32] ints
#define SMEM_G3  189696

// ----------------- device scratch (bss-zeroed at module load) -----------------
__device__ float g_xw  [(size_t)NT*1536];   // input-gate precompute, reused per layer
__device__ float g_bufB[(size_t)NT*512];    // final-layer fp32 activations (pool input)
__device__ int   g_perm[256];               // batch order sorted by length desc
__device__ __nv_bfloat16 g_ah[(size_t)NT*512];   // A hi split (GEMM input)
__device__ __nv_bfloat16 g_al[(size_t)NT*512];   // A lo split
__device__ __nv_bfloat16 g_wh[5*1536*512];       // W hi split, per-layer slots
__device__ __nv_bfloat16 g_wl[5*1536*512];       // W lo split
// h exchange in A-tile layout: [pp][dir][bt][chunk4][row32][col64] bf16
__device__ __nv_bfloat16 g_hxh[2*2*8*4*32*64];
__device__ __nv_bfloat16 g_hxl[2*2*8*4*32*64];

// ----------------- mma.sync helpers (base ISA, compiles at compute_103) -----------------
__device__ __forceinline__ uint32_t smem_u32(const void* p) {
    uint32_t a;
    asm("{ .reg .u64 t; cvta.to.shared.u64 t, %1; cvt.u32.u64 %0, t; }" : "=r"(a) : "l"(p));
    return a;
}
#define SWIZ128(b) ((b) ^ (((b) >> 3) & 0x70))

__device__ __forceinline__ void ldsm4(uint32_t* r, uint32_t addr) {
    asm volatile("ldmatrix.sync.aligned.m8n8.x4.shared.b16 {%0,%1,%2,%3}, [%4];"
                 : "=r"(r[0]), "=r"(r[1]), "=r"(r[2]), "=r"(r[3]) : "r"(addr));
}
__device__ __forceinline__ void ldsm2(uint32_t* r, uint32_t addr) {
    asm volatile("ldmatrix.sync.aligned.m8n8.x2.shared.b16 {%0,%1}, [%2];"
                 : "=r"(r[0]), "=r"(r[1]) : "r"(addr));
}
__device__ __forceinline__ void mma16816(float* c, const uint32_t* a, const uint32_t* b) {
    asm volatile("mma.sync.aligned.m16n8k16.row.col.f32.bf16.bf16.f32 "
                 "{%0,%1,%2,%3}, {%4,%5,%6,%7}, {%8,%9}, {%0,%1,%2,%3};"
                 : "+f"(c[0]), "+f"(c[1]), "+f"(c[2]), "+f"(c[3])
                 : "r"(a[0]), "r"(a[1]), "r"(a[2]), "r"(a[3]), "r"(b[0]), "r"(b[1]));
}
__device__ __forceinline__ void cp16(uint32_t dst, const void* src) {
    asm volatile("cp.async.cg.shared.global [%0], [%1], 16;" :: "r"(dst), "l"(src) : "memory");
}

// fast gates: MUFU-based sigmoid/tanh (err ~1e-6, saturates correctly)
__device__ __forceinline__ float fsig(float x) {
    return __fdividef(1.f, 1.f + __expf(-x));
}
__device__ __forceinline__ float ftanh(float x) {
    return __fdividef(2.f, 1.f + __expf(-2.f*x)) - 1.f;
}

// ----------------- sort batch indices by length descending -----------------
__global__ void halt_sort_perm(const int* __restrict__ lengths) {
    __shared__ int key[256];
    __shared__ int idx[256];
    int tid = threadIdx.x;
    key[tid] = -lengths[tid];
    idx[tid] = tid;
    __syncthreads();
    for (int k = 2; k <= 256; k <<= 1)
        for (int j = k >> 1; j > 0; j >>= 1) {
            int ixj = tid ^ j;
            if (ixj > tid) {
                bool asc = ((tid & k) == 0);
                int a = key[tid], c = key[ixj];
                bool gt = a > c;
                if (asc == gt) {
                    key[tid] = c; key[ixj] = a;
                    int t2 = idx[tid]; idx[tid] = idx[ixj]; idx[ixj] = t2;
                }
            }
            __syncthreads();
        }
    g_perm[tid] = idx[tid];
}

// ----------------- input projection: LN -> Linear -> GELU -> Linear, writes bf16 hi/lo -----------------
__global__ void halt_proj(const float* __restrict__ x, const int* __restrict__ lengths,
                          const float* __restrict__ ln_g, const float* __restrict__ ln_b,
                          const float* __restrict__ w1, const float* __restrict__ b1,
                          const float* __restrict__ w2, const float* __restrict__ b2) {
    int token = blockIdx.x;
    int b = token >> 9, t = token & 511;
    if (t >= lengths[b]) return;
    __shared__ float sx[25], sn[25], sh1[128];
    int tid = threadIdx.x;
    if (tid < 25) sx[tid] = x[(size_t)token*25 + tid];
    __syncthreads();
    float mu = 0.f;
#pragma unroll
    for (int i = 0; i < 25; i++) mu += sx[i];
    mu *= (1.0f/25.0f);
    float var = 0.f;
#pragma unroll
    for (int i = 0; i < 25; i++) { float d = sx[i]-mu; var += d*d; }
    var *= (1.0f/25.0f);
    float rstd = rsqrtf(var + 1e-5f);
    if (tid < 25) sn[tid] = (sx[tid]-mu)*rstd*ln_g[tid] + ln_b[tid];
    __syncthreads();
    float a = b1[tid];
#pragma unroll
    for (int i = 0; i < 25; i++) a += sn[i]*w1[i*128 + tid];
    float ge = 0.5f*a*(1.0f + erff(a*0.70710678118654752440f));
    sh1[tid] = ge;
    __syncthreads();
    float o = b2[tid];
#pragma unroll 8
    for (int i = 0; i < 128; i++) o += sh1[i]*__ldg(&w2[i*128 + tid]);
    __nv_bfloat16 hbf = __float2bfloat16(o);
    g_ah[(size_t)token*128 + tid] = hbf;
    g_al[(size_t)token*128 + tid] = __float2bfloat16(o - __bfloat162float(hbf));
}

// ----------------- fp32 -> bf16 hi/lo split (weights; per-layer slots) -----------------
__global__ void halt_cvt(const float* __restrict__ src, __nv_bfloat16* __restrict__ hi,
                         __nv_bfloat16* __restrict__ lo, size_t n) {
    size_t i = (size_t)blockIdx.x*256 + threadIdx.x;
    if (i >= n) return;
    float v = src[i];
    __nv_bfloat16 h = __float2bfloat16(v);
    hi[i] = h;
    lo[i] = __float2bfloat16(v - __bfloat162float(h));
}

// ----------------- mma.sync GEMM, n-tile 256, cp.async 2-stage pipeline -----------------
__global__ __launch_bounds__(256)
void halt_tcgemm(int K, const __nv_bfloat16* __restrict__ wh, const __nv_bfloat16* __restrict__ wl,
                 const float* __restrict__ bias, const int* __restrict__ lengths) {
    int m0 = blockIdx.x * 128;
    int n0 = blockIdx.y * 256;
    if ((m0 & 511) >= lengths[m0 >> 9]) return;   // fully-padded tile: outputs never read
    extern __shared__ char smem[];
    uint32_t sb = smem_u32(smem);
    int tid = threadIdx.x, warp = tid >> 5, lane = tid & 31;
    int wm = warp & 3, wn = warp >> 2;             // 4 x 2 warp grid, warp tile 32m x 128n

    ((float*)(smem + OFF_BIAS))[tid] = bias[n0 + tid];

    const char* pAh = (const char*)g_ah;
    const char* pAl = (const char*)g_al;
    const char* pBh = (const char*)wh;
    const char* pBl = (const char*)wl;

    float acc[2][16][4];
#pragma unroll
    for (int mi = 0; mi < 2; mi++)
#pragma unroll
        for (int ni = 0; ni < 16; ni++)
#pragma unroll
            for (int q = 0; q < 4; q++) acc[mi][ni][q] = 0.f;

    int arow = wm*32 + (lane & 15);
    int acolsel = (lane >> 4) * 8;
    int brow = wn*128 + (lane & 7) + ((lane & 16) ? 8 : 0);
    int bcolsel = (lane & 8) ? 8 : 0;

    int nchunks = K >> 6;
    auto stage = [&](int c, int buf) {
        uint32_t base = sb + buf*TCG_STAGE;
        for (int it = tid; it < 1024; it += 256) {
            int r = it >> 3, u = it & 7;
            uint32_t sw = SWIZ128((uint32_t)(r*128 + u*16));
            size_t ga = ((size_t)(m0 + r)*K + c*64)*2 + u*16;
            cp16(base + 0     + sw, pAh + ga);
            cp16(base + 16384 + sw, pAl + ga);
        }
        for (int it = tid; it < 2048; it += 256) {
            int r = it >> 3, u = it & 7;
            uint32_t sw = SWIZ128((uint32_t)(r*128 + u*16));
            size_t gb = ((size_t)(n0 + r)*K + c*64)*2 + u*16;
            cp16(base + 32768 + sw, pBh + gb);
            cp16(base + 65536 + sw, pBl + gb);
        }
        asm volatile("cp.async.commit_group;" ::: "memory");
    };

    stage(0, 0);
    for (int c = 0; c < nchunks; c++) {
        int buf = c & 1;
        if (c + 1 < nchunks) {
            stage(c + 1, buf ^ 1);
            asm volatile("cp.async.wait_group 1;" ::: "memory");
        } else {
            asm volatile("cp.async.wait_group 0;" ::: "memory");
        }
        __syncthreads();
        uint32_t base = sb + buf*TCG_STAGE;
#pragma unroll
        for (int ks = 0; ks < 4; ks++) {
            int kc = ks*16;
            uint32_t ah[2][4], al[2][4];
#pragma unroll
            for (int mi = 0; mi < 2; mi++) {
                uint32_t off = SWIZ128((uint32_t)((arow + mi*16)*128 + (kc + acolsel)*2));
                ldsm4(ah[mi], base + 0     + off);
                ldsm4(al[mi], base + 16384 + off);
            }
#pragma unroll
            for (int ph = 0; ph < 2; ph++) {
                uint32_t bh[4][4], bl[4][4];
#pragma unroll
                for (int p = 0; p < 4; p++) {
                    int pp = ph*4 + p;
                    uint32_t off = SWIZ128((uint32_t)((brow + pp*16)*128 + (kc + bcolsel)*2));
                    ldsm4(bh[p], base + 32768 + off);
                    ldsm4(bl[p], base + 65536 + off);
                }
#pragma unroll
                for (int mi = 0; mi < 2; mi++)
#pragma unroll
                    for (int p = 0; p < 4; p++) {
                        int ni = ph*8 + 2*p;
                        mma16816(acc[mi][ni],   ah[mi], &bh[p][0]);
                        mma16816(acc[mi][ni],   ah[mi], &bl[p][0]);
                        mma16816(acc[mi][ni],   al[mi], &bh[p][0]);
                        mma16816(acc[mi][ni+1], ah[mi], &bh[p][2]);
                        mma16816(acc[mi][ni+1], ah[mi], &bl[p][2]);
                        mma16816(acc[mi][ni+1], al[mi], &bh[p][2]);
                    }
            }
        }
        __syncthreads();
    }

    const float* sbias = (const float*)(smem + OFF_BIAS);
#pragma unroll
    for (int mi = 0; mi < 2; mi++) {
        int rw = m0 + wm*32 + mi*16 + (lane >> 2);
#pragma unroll
        for (int ni = 0; ni < 16; ni++) {
            int cw = wn*128 + ni*8 + (lane & 3)*2;
            float bx = sbias[cw], by = sbias[cw + 1];
            float2 v0 = { acc[mi][ni][0] + bx, acc[mi][ni][1] + by };
            float2 v1 = { acc[mi][ni][2] + bx, acc[mi][ni][3] + by };
            *(float2*)&g_xw[(size_t)rw*1536 + n0 + cw]       = v0;
            *(float2*)&g_xw[(size_t)(rw + 8)*1536 + n0 + cw] = v1;
        }
    }
}

// ----------------- GRU v8: coalesced smem xw staging (double-buffered, prefetch 1 step) ---------
// 128 blocks = 2 dir x 8 bt x 8 hc(32 j); cluster = 8 hc blocks of one (dir,bt).
__global__ __launch_bounds__(256, 1) __cluster_dims__(8, 1, 1)
void halt_gru3(const float* __restrict__ xw, float* __restrict__ y,
               const float* __restrict__ Whh, const float* __restrict__ bhh,
               const int* __restrict__ lengths, int last) {
    extern __shared__ char smg[];
    uint32_t sb = smem_u32(smg);
    float* xsm = (float*)(smg + OFF_XW);       // [2][32][100]
    int* spb   = (int*)(smg + OFF_META);       // [32]
    int* slen  = spb + 32;                     // [32]
    int grp = blockIdx.x >> 3;
    int hc  = blockIdx.x & 7;
    int dir = grp >> 3;
    int bt  = grp & 7;
    int j0  = hc * 32;
    int tid = threadIdx.x;
    int warp = tid >> 5, lane = tid & 31;
    int wm = warp >> 2, wn = warp & 3;

    // load Whh slice -> smem bf16 hi/lo, [4 chunks][96 rows][64], SW128
    const float* Wd = Whh + (size_t)dir*768*256;
    for (int idx = tid; idx < 96*256; idx += 256) {
        int r = idx >> 8, k = idx & 255;
        int g = r >> 5, jl = r & 31;
        float w = Wd[(size_t)(g*256 + j0 + jl)*256 + k];
        __nv_bfloat16 h = __float2bfloat16(w);
        __nv_bfloat16 l = __float2bfloat16(w - __bfloat162float(h));
        int chunk = k >> 6;
        uint32_t sw = SWIZ128((uint32_t)(r*128 + (k & 63)*2));
        *(__nv_bfloat16*)(smg + OFF_WH + chunk*16384 + sw) = h;
        *(__nv_bfloat16*)(smg + OFF_WL + chunk*16384 + sw) = l;
    }
    if (tid < 32) {
        int pbv = g_perm[bt*32 + tid];
        spb[tid]  = pbv;
        slen[tid] = lengths[pbv];
    }
    __syncthreads();

    // element mapping: thread owns (s_a, jc..jc+1), (s_a+8, jc..jc+1)
    int sa = wm*16 + (lane >> 2);
    int jc = wn*8 + (lane & 3)*2;
    int jcg = j0 + jc;
    float bhr0 = bhh[dir*768 +       jcg], bhr1 = bhh[dir*768 +       jcg + 1];
    float bhz0 = bhh[dir*768 + 256 + jcg], bhz1 = bhh[dir*768 + 256 + jcg + 1];
    float bhn0 = bhh[dir*768 + 512 + jcg], bhn1 = bhh[dir*768 + 512 + jcg + 1];
    int pb2[2], lenv2[2];
#pragma unroll
    for (int si = 0; si < 2; si++) {
        pb2[si]   = spb[sa + si*8];
        lenv2[si] = slen[sa + si*8];
    }
    int tmax = slen[0];                    // sorted desc -> same across cluster

    // merged B fragment addressing
    int m4 = lane >> 3;
    int g4 = m4 >> 1, kh4 = (m4 & 1) * 8;
    int row4 = g4*32 + wn*8 + (lane & 7);
    int lx = lane & 15;
    int brx = lx & 7, bsel = (lx & 8) ? 8 : 0;
    int row2 = 64 + wn*8 + brx;

    // cache static B-hi weight fragments in regs: [16 k16][3 gates][2]
    uint32_t Bh[16][6];
#pragma unroll
    for (int k16 = 0; k16 < 16; k16++) {
        int chunk = k16 >> 2, kc = (k16 & 3)*16;
        uint32_t off4 = SWIZ128((uint32_t)(row4*128 + (kc + kh4)*2));
        ldsm4(&Bh[k16][0], sb + OFF_WH + chunk*16384 + off4);
        uint32_t off2 = SWIZ128((uint32_t)(row2*128 + (kc + bsel)*2));
        ldsm2(&Bh[k16][4], sb + OFF_WH + chunk*16384 + off2);
    }

    int arow = wm*16 + (lane & 15);
    int acolsel = (lane >> 4) * 8;
    int jchunk = jcg >> 6;

    float hprev[4] = {0.f, 0.f, 0.f, 0.f};

    // coalesced xw staging: 96 lines of 128B (32 samples x 3 gates x 32 floats), 3 cp16/thread
    auto xwstage = [&](int tt, int buf) {
#pragma unroll
        for (int q = 0; q < 3; q++) {
            int it = tid + q*256;            // 0..767
            int line = it >> 3, u = it & 7;  // line 0..95
            int s = line / 3, g = line - s*3;
            int len_s = slen[s];
            if (tt < len_s) {
                int tk = dir ? (len_s - 1 - tt) : tt;
                const char* src = (const char*)(xw + ((size_t)spb[s]*512 + tk)*1536
                                                + dir*768 + g*256 + j0) + u*16;
                cp16(sb + OFF_XW + (uint32_t)(buf*12800 + s*400 + g*128 + u*16), src);
            }
        }
        asm volatile("cp.async.commit_group;" ::: "memory");
    };
    xwstage(0, 0);   // prefetch step 0

    for (int t = 0; t < tmax; t++) {
        int buf = t & 1;
        // phase 1: cp.async copy of peer-written A tiles (already swizzled layout)
        size_t tb = ((size_t)((t & 1)*2 + dir)*8 + bt) * 16384;
        const char* srch = (const char*)g_hxh + tb;
        const char* srcl = (const char*)g_hxl + tb;
#pragma unroll
        for (int q = 0; q < 4; q++) {
            int it = (tid + q*256) * 16;
            cp16(sb + OFF_AH2 + it, srch + it);
            cp16(sb + OFF_AL2 + it, srcl + it);
        }
        asm volatile("cp.async.commit_group;" ::: "memory");
        // prefetch xw for NEXT step (left in flight across this step's compute)
        xwstage(t + 1, buf ^ 1);
        asm volatile("cp.async.wait_group 1;" ::: "memory");   // exchange + xw(t) complete
        __syncthreads();

        // phase 2: mma — A ldsm + B-lo (ldsm4+ldsm2), B-hi from registers; gate-aligned acc
        float acc[3][4];
#pragma unroll
        for (int g = 0; g < 3; g++) { acc[g][0]=0.f; acc[g][1]=0.f; acc[g][2]=0.f; acc[g][3]=0.f; }
#pragma unroll
        for (int k16 = 0; k16 < 16; k16++) {
            int chunk = k16 >> 2, kc = (k16 & 3)*16;
            uint32_t asw = SWIZ128((uint32_t)(arow*128 + (kc + acolsel)*2));
            uint32_t ah[4], al[4];
            ldsm4(ah, sb + OFF_AH2 + chunk*4096 + asw);
            ldsm4(al, sb + OFF_AL2 + chunk*4096 + asw);
            uint32_t bl[6];
            uint32_t off4 = SWIZ128((uint32_t)(row4*128 + (kc + kh4)*2));
            ldsm4(&bl[0], sb + OFF_WL + chunk*16384 + off4);
            uint32_t off2 = SWIZ128((uint32_t)(row2*128 + (kc + bsel)*2));
            ldsm2(&bl[4], sb + OFF_WL + chunk*16384 + off2);
#pragma unroll
            for (int g = 0; g < 3; g++) {
                mma16816(acc[g], ah, &Bh[k16][g*2]);
                mma16816(acc[g], ah, &bl[g*2]);
                mma16816(acc[g], al, &Bh[k16][g*2]);
            }
        }

        // phase 3a: gates (xw from smem); update hprev; store peer-consumed h exchange tiles
        size_t tbn = ((size_t)(((t+1) & 1)*2 + dir)*8 + bt) * 16384;
        uint32_t hpv[2], lpv[2];
        int tok[2];
#pragma unroll
        for (int si = 0; si < 2; si++) {
            if (t < lenv2[si]) {
                int e = si*2;
                int s = sa + si*8;
                const float* xq = &xsm[buf*3200 + s*100 + jc];
                float2 xrv = *(const float2*)(xq);
                float2 xzv = *(const float2*)(xq + 32);
                float2 xnv = *(const float2*)(xq + 64);
                float r0 = fsig(xrv.x + acc[0][e]   + bhr0);
                float r1 = fsig(xrv.y + acc[0][e+1] + bhr1);
                float z0 = fsig(xzv.x + acc[1][e]   + bhz0);
                float z1 = fsig(xzv.y + acc[1][e+1] + bhz1);
                float n0 = ftanh(xnv.x + r0*(acc[2][e]   + bhn0));
                float n1 = ftanh(xnv.y + r1*(acc[2][e+1] + bhn1));
                float h0 = (1.f - z0)*n0 + z0*hprev[e];
                float h1 = (1.f - z1)*n1 + z1*hprev[e+1];
                hprev[e] = h0; hprev[e+1] = h1;
                __nv_bfloat16 hb0 = __float2bfloat16(h0);
                __nv_bfloat16 hb1 = __float2bfloat16(h1);
                __nv_bfloat16 lb0 = __float2bfloat16(h0 - __bfloat162float(hb0));
                __nv_bfloat16 lb1 = __float2bfloat16(h1 - __bfloat162float(hb1));
                hpv[si] = (uint32_t)__bfloat16_as_ushort(hb0) | ((uint32_t)__bfloat16_as_ushort(hb1) << 16);
                lpv[si] = (uint32_t)__bfloat16_as_ushort(lb0) | ((uint32_t)__bfloat16_as_ushort(lb1) << 16);
                tok[si] = dir ? (lenv2[si] - 1 - t) : t;
                uint32_t sw = SWIZ128((uint32_t)(s*128 + (jcg & 63)*2));
                *(uint32_t*)((char*)g_hxh + tbn + jchunk*4096 + sw) = hpv[si];
                *(uint32_t*)((char*)g_hxl + tbn + jchunk*4096 + sw) = lpv[si];
            }
        }
        // arrive early (releases our exchange stores), overlap non-peer work, then wait
        asm volatile("barrier.cluster.arrive.aligned;" ::: "memory");
#pragma unroll
        for (int si = 0; si < 2; si++) {
            if (t < lenv2[si]) {
                size_t oc = ((size_t)pb2[si]*512 + tok[si])*512 + dir*256 + jcg;
                if (last) {
                    float2 hv;
                    hv.x = __bfloat162float(__ushort_as_bfloat16((unsigned short)(hpv[si] & 0xffff)))
                         + __bfloat162float(__ushort_as_bfloat16((unsigned short)(lpv[si] & 0xffff)));
                    hv.y = __bfloat162float(__ushort_as_bfloat16((unsigned short)(hpv[si] >> 16)))
                         + __bfloat162float(__ushort_as_bfloat16((unsigned short)(lpv[si] >> 16)));
                    *(float2*)&y[oc] = hv;
                } else {
                    *(uint32_t*)&g_ah[oc] = hpv[si];
                    *(uint32_t*)&g_al[oc] = lpv[si];
                }
            }
        }
        asm volatile("barrier.cluster.wait.aligned;" ::: "memory");
    }
}

// ----------------- top-k pooling + classifier -----------------
__global__ __launch_bounds__(256)
void halt_pool(const float* __restrict__ H, const int* __restrict__ lengths,
               const float* __restrict__ Wc, const float* __restrict__ bc,
               float* __restrict__ out) {
    int b = blockIdx.x, tid = threadIdx.x;
    __shared__ float ns[512];
    __shared__ int   si[512];
    __shared__ float red[256];
    int len = lengths[b];
    int warp = tid >> 5, lane = tid & 31;
    for (int r = warp; r < 512; r += 8) {
        float sc = 1e9f;
        if (r < len) {
            const float* row = H + ((size_t)b*512 + r)*512;
            float acc = 0.f;
#pragma unroll 4
            for (int d = lane; d < 512; d += 32) { float v = row[d]; acc += v*v; }
#pragma unroll
            for (int o = 16; o > 0; o >>= 1) acc += __shfl_xor_sync(0xffffffffu, acc, o);
            sc = -sqrtf(acc);
        }
        if (lane == 0) { ns[r] = sc; si[r] = r; }
    }
    __syncthreads();
    for (int k = 2; k <= 512; k <<= 1)
        for (int j = k >> 1; j > 0; j >>= 1) {
            for (int i = tid; i < 512; i += 256) {
                int ixj = i ^ j;
                if (ixj > i) {
                    bool asc = ((i & k) == 0);
                    float a = ns[i], c = ns[ixj];
                    int ia = si[i], ic = si[ixj];
                    bool gt = (a > c) || (a == c && ia > ic);
                    if (asc == gt) { ns[i] = c; ns[ixj] = a; si[i] = ic; si[ixj] = ia; }
                }
            }
            __syncthreads();
        }
    int kk = (int)ceilf((float)len * 0.15f);
    if (kk < 1) kk = 1;
    float a0 = 0.f, a1 = 0.f;
    for (int i = 0; i < kk; i++) {
        int r = si[i];
        const float* row = H + ((size_t)b*512 + r)*512;
        a0 += row[tid]; a1 += row[tid + 256];
    }
    float kf = (float)kk;
    float part = (a0/kf)*Wc[tid] + (a1/kf)*Wc[tid + 256];
    red[tid] = part;
    __syncthreads();
    for (int s2 = 128; s2 > 0; s2 >>= 1) {
        if (tid < s2) red[tid] += red[tid + s2];
        __syncthreads();
    }
    if (tid == 0) out[b] = red[0] + bc[0];
}

// ----------------- host orchestration -----------------
extern "C" void kernel_launch(void* const* d_in, const int* in_sizes, int n_in,
                              void* d_out, int out_size) {
    const float* x    = (const float*)d_in[0];
    const int*   lens = (const int*)  d_in[1];
    const float* ln_g = (const float*)d_in[2];
    const float* ln_b = (const float*)d_in[3];
    const float* w1   = (const float*)d_in[4];
    const float* b1   = (const float*)d_in[5];
    const float* w2   = (const float*)d_in[6];
    const float* b2   = (const float*)d_in[7];
    const float* Wih0 = (const float*)d_in[8];
    const float* Whh0 = (const float*)d_in[9];
    const float* bih0 = (const float*)d_in[10];
    const float* bhh0 = (const float*)d_in[11];
    const float* Wih  = (const float*)d_in[12];
    const float* Whh  = (const float*)d_in[13];
    const float* bih  = (const float*)d_in[14];
    const float* bhh  = (const float*)d_in[15];
    const float* Wc   = (const float*)d_in[16];
    const float* bc   = (const float*)d_in[17];
    float* out = (float*)d_out;

    cudaFuncSetAttribute(halt_gru3, cudaFuncAttributeMaxDynamicSharedMemorySize, SMEM_G3);
    cudaFuncSetAttribute(halt_tcgemm, cudaFuncAttributeMaxDynamicSharedMemorySize, SMEM_TC);

    void *pB = 0, *pxw = 0, *pwh = 0, *pwl = 0, *phxh = 0, *phxl = 0;
    cudaGetSymbolAddress(&pB,   g_bufB);
    cudaGetSymbolAddress(&pxw,  g_xw);
    cudaGetSymbolAddress(&pwh,  g_wh);
    cudaGetSymbolAddress(&pwl,  g_wl);
    cudaGetSymbolAddress(&phxh, g_hxh);
    cudaGetSymbolAddress(&phxl, g_hxl);
    float* fB  = (float*)pB;
    float* fxw = (float*)pxw;

    halt_sort_perm<<<1, 256>>>(lens);
    halt_proj<<<NT, 128>>>(x, lens, ln_g, ln_b, w1, b1, w2, b2);

    for (int l = 0; l < 5; l++) {
        const float* Wi = l ? (Wih + (size_t)(l-1)*2*768*512) : Wih0;
        int K = l ? 512 : 128;
        size_t nW = (size_t)1536 * K;
        __nv_bfloat16* wh = (__nv_bfloat16*)pwh + (size_t)l*1536*512;
        __nv_bfloat16* wl = (__nv_bfloat16*)pwl + (size_t)l*1536*512;
        halt_cvt<<<(unsigned)((nW + 255)/256), 256>>>(Wi, wh, wl, nW);
    }

    for (int l = 0; l < 5; l++) {
        const float* bi = l ? (bih + (l-1)*1536) : bih0;
        const float* Wh = l ? (Whh + (size_t)(l-1)*2*768*256) : Whh0;
        const float* bh = l ? (bhh + (l-1)*1536) : bhh0;
        int K = l ? 512 : 128;
        const __nv_bfloat16* wh = (const __nv_bfloat16*)pwh + (size_t)l*1536*512;
        const __nv_bfloat16* wl = (const __nv_bfloat16*)pwl + (size_t)l*1536*512;

        cudaMemsetAsync(phxh, 0, (size_t)2*2*8*4*32*64*sizeof(__nv_bfloat16));
        cudaMemsetAsync(phxl, 0, (size_t)2*2*8*4*32*64*sizeof(__nv_bfloat16));

        dim3 gg(NT/128, 6);
        halt_tcgemm<<<gg, 256, SMEM_TC>>>(K, wh, wl, bi, lens);

        halt_gru3<<<128, 256, SMEM_G3>>>(fxw, fB, Wh, bh, lens, (l == 4) ? 1 : 0);
    }
    halt_pool<<<256, 256>>>(fB, lens, Wc, bc, out);
}

// round 17
// speedup vs baseline: 1.5624x; 1.1292x over previous
#include <cuda_runtime.h>
#include <cuda_bf16.h>
#include <cuda_fp16.h>
#include <math.h>
#include <stdint.h>

#define Bn   256
#define Tn   512
#define NT   (Bn*Tn)          // 131072 tokens

// tcgemm smem: 2 stages x (A hi/lo 16KB each + B hi/lo 32KB each) + bias
#define TCG_STAGE  98304
#define OFF_BIAS   196608
#define SMEM_TC    (196608 + 1024)

// GRU smem (bytes)
#define OFF_WH   0                    // Whh fp16 hi [4 chunks][96 rows][64]
#define OFF_WL   65536                // Whh fp16 lo
#define OFF_A    131072               // h fp16 [4 chunks][32 rows][64]
#define OFF_XW   147456               // xw stage: 2 bufs x [32 s][100 floats]
#define OFF_META 173056               // pb[32], len[32] ints
#define SMEM_G3  173312

// ----------------- device scratch (bss-zeroed at module load) -----------------
__device__ float g_xw  [(size_t)NT*1536];   // input-gate precompute, reused per layer
__device__ float g_bufB[(size_t)NT*512];    // final-layer fp32 activations (pool input)
__device__ int   g_perm[256];               // batch order sorted by length desc
__device__ __nv_bfloat16 g_ah[(size_t)NT*512];   // A hi split (GEMM input, bf16)
__device__ __nv_bfloat16 g_al[(size_t)NT*512];   // A lo split
__device__ __nv_bfloat16 g_wh[5*1536*512];       // GEMM W hi split, per-layer slots
__device__ __nv_bfloat16 g_wl[5*1536*512];       // GEMM W lo split
// h exchange in A-tile layout, single fp16: [pp][dir][bt][chunk4][row32][col64]
__device__ __half g_hx[2*2*8*4*32*64];

// ----------------- mma.sync helpers (base ISA, compiles at compute_103) -----------------
__device__ __forceinline__ uint32_t smem_u32(const void* p) {
    uint32_t a;
    asm("{ .reg .u64 t; cvta.to.shared.u64 t, %1; cvt.u32.u64 %0, t; }" : "=r"(a) : "l"(p));
    return a;
}
#define SWIZ128(b) ((b) ^ (((b) >> 3) & 0x70))

__device__ __forceinline__ void ldsm4(uint32_t* r, uint32_t addr) {
    asm volatile("ldmatrix.sync.aligned.m8n8.x4.shared.b16 {%0,%1,%2,%3}, [%4];"
                 : "=r"(r[0]), "=r"(r[1]), "=r"(r[2]), "=r"(r[3]) : "r"(addr));
}
__device__ __forceinline__ void ldsm2(uint32_t* r, uint32_t addr) {
    asm volatile("ldmatrix.sync.aligned.m8n8.x2.shared.b16 {%0,%1}, [%2];"
                 : "=r"(r[0]), "=r"(r[1]) : "r"(addr));
}
__device__ __forceinline__ void mma_bf(float* c, const uint32_t* a, const uint32_t* b) {
    asm volatile("mma.sync.aligned.m16n8k16.row.col.f32.bf16.bf16.f32 "
                 "{%0,%1,%2,%3}, {%4,%5,%6,%7}, {%8,%9}, {%0,%1,%2,%3};"
                 : "+f"(c[0]), "+f"(c[1]), "+f"(c[2]), "+f"(c[3])
                 : "r"(a[0]), "r"(a[1]), "r"(a[2]), "r"(a[3]), "r"(b[0]), "r"(b[1]));
}
__device__ __forceinline__ void mma_hf(float* c, const uint32_t* a, const uint32_t* b) {
    asm volatile("mma.sync.aligned.m16n8k16.row.col.f32.f16.f16.f32 "
                 "{%0,%1,%2,%3}, {%4,%5,%6,%7}, {%8,%9}, {%0,%1,%2,%3};"
                 : "+f"(c[0]), "+f"(c[1]), "+f"(c[2]), "+f"(c[3])
                 : "r"(a[0]), "r"(a[1]), "r"(a[2]), "r"(a[3]), "r"(b[0]), "r"(b[1]));
}
__device__ __forceinline__ void cp16(uint32_t dst, const void* src) {
    asm volatile("cp.async.cg.shared.global [%0], [%1], 16;" :: "r"(dst), "l"(src) : "memory");
}

// fast gates: MUFU-based sigmoid/tanh (err ~1e-6, saturates correctly)
__device__ __forceinline__ float fsig(float x) {
    return __fdividef(1.f, 1.f + __expf(-x));
}
__device__ __forceinline__ float ftanh(float x) {
    return __fdividef(2.f, 1.f + __expf(-2.f*x)) - 1.f;
}

// ----------------- sort batch indices by length descending -----------------
__global__ void halt_sort_perm(const int* __restrict__ lengths) {
    __shared__ int key[256];
    __shared__ int idx[256];
    int tid = threadIdx.x;
    key[tid] = -lengths[tid];
    idx[tid] = tid;
    __syncthreads();
    for (int k = 2; k <= 256; k <<= 1)
        for (int j = k >> 1; j > 0; j >>= 1) {
            int ixj = tid ^ j;
            if (ixj > tid) {
                bool asc = ((tid & k) == 0);
                int a = key[tid], c = key[ixj];
                bool gt = a > c;
                if (asc == gt) {
                    key[tid] = c; key[ixj] = a;
                    int t2 = idx[tid]; idx[tid] = idx[ixj]; idx[ixj] = t2;
                }
            }
            __syncthreads();
        }
    g_perm[tid] = idx[tid];
}

// ----------------- input projection: LN -> Linear -> GELU -> Linear, writes bf16 hi/lo ----------
__global__ void halt_proj(const float* __restrict__ x, const int* __restrict__ lengths,
                          const float* __restrict__ ln_g, const float* __restrict__ ln_b,
                          const float* __restrict__ w1, const float* __restrict__ b1,
                          const float* __restrict__ w2, const float* __restrict__ b2) {
    int token = blockIdx.x;
    int b = token >> 9, t = token & 511;
    if (t >= lengths[b]) return;
    __shared__ float sx[25], sn[25], sh1[128];
    int tid = threadIdx.x;
    if (tid < 25) sx[tid] = x[(size_t)token*25 + tid];
    __syncthreads();
    float mu = 0.f;
#pragma unroll
    for (int i = 0; i < 25; i++) mu += sx[i];
    mu *= (1.0f/25.0f);
    float var = 0.f;
#pragma unroll
    for (int i = 0; i < 25; i++) { float d = sx[i]-mu; var += d*d; }
    var *= (1.0f/25.0f);
    float rstd = rsqrtf(var + 1e-5f);
    if (tid < 25) sn[tid] = (sx[tid]-mu)*rstd*ln_g[tid] + ln_b[tid];
    __syncthreads();
    float a = b1[tid];
#pragma unroll
    for (int i = 0; i < 25; i++) a += sn[i]*w1[i*128 + tid];
    float ge = 0.5f*a*(1.0f + erff(a*0.70710678118654752440f));
    sh1[tid] = ge;
    __syncthreads();
    float o = b2[tid];
#pragma unroll 8
    for (int i = 0; i < 128; i++) o += sh1[i]*__ldg(&w2[i*128 + tid]);
    __nv_bfloat16 hbf = __float2bfloat16(o);
    g_ah[(size_t)token*128 + tid] = hbf;
    g_al[(size_t)token*128 + tid] = __float2bfloat16(o - __bfloat162float(hbf));
}

// ----------------- fp32 -> bf16 hi/lo split (GEMM weights; per-layer slots) -----------------
__global__ void halt_cvt(const float* __restrict__ src, __nv_bfloat16* __restrict__ hi,
                         __nv_bfloat16* __restrict__ lo, size_t n) {
    size_t i = (size_t)blockIdx.x*256 + threadIdx.x;
    if (i >= n) return;
    float v = src[i];
    __nv_bfloat16 h = __float2bfloat16(v);
    hi[i] = h;
    lo[i] = __float2bfloat16(v - __bfloat162float(h));
}

// ----------------- mma.sync GEMM, n-tile 256, bf16 3-chain, cp.async pipeline -----------------
__global__ __launch_bounds__(256)
void halt_tcgemm(int K, const __nv_bfloat16* __restrict__ wh, const __nv_bfloat16* __restrict__ wl,
                 const float* __restrict__ bias, const int* __restrict__ lengths) {
    int m0 = blockIdx.x * 128;
    int n0 = blockIdx.y * 256;
    if ((m0 & 511) >= lengths[m0 >> 9]) return;   // fully-padded tile: outputs never read
    extern __shared__ char smem[];
    uint32_t sb = smem_u32(smem);
    int tid = threadIdx.x, warp = tid >> 5, lane = tid & 31;
    int wm = warp & 3, wn = warp >> 2;             // 4 x 2 warp grid, warp tile 32m x 128n

    ((float*)(smem + OFF_BIAS))[tid] = bias[n0 + tid];

    const char* pAh = (const char*)g_ah;
    const char* pAl = (const char*)g_al;
    const char* pBh = (const char*)wh;
    const char* pBl = (const char*)wl;

    float acc[2][16][4];
#pragma unroll
    for (int mi = 0; mi < 2; mi++)
#pragma unroll
        for (int ni = 0; ni < 16; ni++)
#pragma unroll
            for (int q = 0; q < 4; q++) acc[mi][ni][q] = 0.f;

    int arow = wm*32 + (lane & 15);
    int acolsel = (lane >> 4) * 8;
    int brow = wn*128 + (lane & 7) + ((lane & 16) ? 8 : 0);
    int bcolsel = (lane & 8) ? 8 : 0;

    int nchunks = K >> 6;
    auto stage = [&](int c, int buf) {
        uint32_t base = sb + buf*TCG_STAGE;
        for (int it = tid; it < 1024; it += 256) {
            int r = it >> 3, u = it & 7;
            uint32_t sw = SWIZ128((uint32_t)(r*128 + u*16));
            size_t ga = ((size_t)(m0 + r)*K + c*64)*2 + u*16;
            cp16(base + 0     + sw, pAh + ga);
            cp16(base + 16384 + sw, pAl + ga);
        }
        for (int it = tid; it < 2048; it += 256) {
            int r = it >> 3, u = it & 7;
            uint32_t sw = SWIZ128((uint32_t)(r*128 + u*16));
            size_t gb = ((size_t)(n0 + r)*K + c*64)*2 + u*16;
            cp16(base + 32768 + sw, pBh + gb);
            cp16(base + 65536 + sw, pBl + gb);
        }
        asm volatile("cp.async.commit_group;" ::: "memory");
    };

    stage(0, 0);
    for (int c = 0; c < nchunks; c++) {
        int buf = c & 1;
        if (c + 1 < nchunks) {
            stage(c + 1, buf ^ 1);
            asm volatile("cp.async.wait_group 1;" ::: "memory");
        } else {
            asm volatile("cp.async.wait_group 0;" ::: "memory");
        }
        __syncthreads();
        uint32_t base = sb + buf*TCG_STAGE;
#pragma unroll
        for (int ks = 0; ks < 4; ks++) {
            int kc = ks*16;
            uint32_t ah[2][4], al[2][4];
#pragma unroll
            for (int mi = 0; mi < 2; mi++) {
                uint32_t off = SWIZ128((uint32_t)((arow + mi*16)*128 + (kc + acolsel)*2));
                ldsm4(ah[mi], base + 0     + off);
                ldsm4(al[mi], base + 16384 + off);
            }
#pragma unroll
            for (int ph = 0; ph < 2; ph++) {
                uint32_t bh[4][4], bl[4][4];
#pragma unroll
                for (int p = 0; p < 4; p++) {
                    int pp = ph*4 + p;
                    uint32_t off = SWIZ128((uint32_t)((brow + pp*16)*128 + (kc + bcolsel)*2));
                    ldsm4(bh[p], base + 32768 + off);
                    ldsm4(bl[p], base + 65536 + off);
                }
#pragma unroll
                for (int mi = 0; mi < 2; mi++)
#pragma unroll
                    for (int p = 0; p < 4; p++) {
                        int ni = ph*8 + 2*p;
                        mma_bf(acc[mi][ni],   ah[mi], &bh[p][0]);
                        mma_bf(acc[mi][ni],   ah[mi], &bl[p][0]);
                        mma_bf(acc[mi][ni],   al[mi], &bh[p][0]);
                        mma_bf(acc[mi][ni+1], ah[mi], &bh[p][2]);
                        mma_bf(acc[mi][ni+1], ah[mi], &bl[p][2]);
                        mma_bf(acc[mi][ni+1], al[mi], &bh[p][2]);
                    }
            }
        }
        __syncthreads();
    }

    const float* sbias = (const float*)(smem + OFF_BIAS);
#pragma unroll
    for (int mi = 0; mi < 2; mi++) {
        int rw = m0 + wm*32 + mi*16 + (lane >> 2);
#pragma unroll
        for (int ni = 0; ni < 16; ni++) {
            int cw = wn*128 + ni*8 + (lane & 3)*2;
            float bx = sbias[cw], by = sbias[cw + 1];
            float2 v0 = { acc[mi][ni][0] + bx, acc[mi][ni][1] + by };
            float2 v1 = { acc[mi][ni][2] + bx, acc[mi][ni][3] + by };
            *(float2*)&g_xw[(size_t)rw*1536 + n0 + cw]       = v0;
            *(float2*)&g_xw[(size_t)(rw + 8)*1536 + n0 + cw] = v1;
        }
    }
}

// ----------------- GRU v10: fp16 h (single) x fp16 hi/lo W, 6 mma/k16 -----------------
// 128 blocks = 2 dir x 8 bt x 8 hc(32 j); cluster = 8 hc blocks of one (dir,bt).
__global__ __launch_bounds__(256, 1) __cluster_dims__(8, 1, 1)
void halt_gru3(const float* __restrict__ xw, float* __restrict__ y,
               const float* __restrict__ Whh, const float* __restrict__ bhh,
               const int* __restrict__ lengths, int last) {
    extern __shared__ char smg[];
    uint32_t sb = smem_u32(smg);
    float* xsm = (float*)(smg + OFF_XW);       // [2][32][100]
    int* spb   = (int*)(smg + OFF_META);       // [32]
    int* slen  = spb + 32;                     // [32]
    int grp = blockIdx.x >> 3;
    int hc  = blockIdx.x & 7;
    int dir = grp >> 3;
    int bt  = grp & 7;
    int j0  = hc * 32;
    int tid = threadIdx.x;
    int warp = tid >> 5, lane = tid & 31;
    int wm = warp >> 2, wn = warp & 3;

    // load Whh slice -> smem fp16 hi/lo, [4 chunks][96 rows][64], SW128
    const float* Wd = Whh + (size_t)dir*768*256;
    for (int idx = tid; idx < 96*256; idx += 256) {
        int r = idx >> 8, k = idx & 255;
        int g = r >> 5, jl = r & 31;
        float w = Wd[(size_t)(g*256 + j0 + jl)*256 + k];
        __half h = __float2half(w);
        __half l = __float2half(w - __half2float(h));
        int chunk = k >> 6;
        uint32_t sw = SWIZ128((uint32_t)(r*128 + (k & 63)*2));
        *(__half*)(smg + OFF_WH + chunk*16384 + sw) = h;
        *(__half*)(smg + OFF_WL + chunk*16384 + sw) = l;
    }
    if (tid < 32) {
        int pbv = g_perm[bt*32 + tid];
        spb[tid]  = pbv;
        slen[tid] = lengths[pbv];
    }
    __syncthreads();

    // element mapping: thread owns (s_a, jc..jc+1), (s_a+8, jc..jc+1)
    int sa = wm*16 + (lane >> 2);
    int jc = wn*8 + (lane & 3)*2;
    int jcg = j0 + jc;
    float bhr0 = bhh[dir*768 +       jcg], bhr1 = bhh[dir*768 +       jcg + 1];
    float bhz0 = bhh[dir*768 + 256 + jcg], bhz1 = bhh[dir*768 + 256 + jcg + 1];
    float bhn0 = bhh[dir*768 + 512 + jcg], bhn1 = bhh[dir*768 + 512 + jcg + 1];
    int pb2[2], lenv2[2];
#pragma unroll
    for (int si = 0; si < 2; si++) {
        pb2[si]   = spb[sa + si*8];
        lenv2[si] = slen[sa + si*8];
    }
    int tmax = slen[0];                    // sorted desc -> same across cluster

    // merged B fragment addressing
    int m4 = lane >> 3;
    int g4 = m4 >> 1, kh4 = (m4 & 1) * 8;
    int row4 = g4*32 + wn*8 + (lane & 7);
    int lx = lane & 15;
    int brx = lx & 7, bsel = (lx & 8) ? 8 : 0;
    int row2 = 64 + wn*8 + brx;

    // cache W-hi fragments in regs: [16 k16][3 gates][2]
    uint32_t Bh[16][6];
#pragma unroll
    for (int k16 = 0; k16 < 16; k16++) {
        int chunk = k16 >> 2, kc = (k16 & 3)*16;
        uint32_t off4 = SWIZ128((uint32_t)(row4*128 + (kc + kh4)*2));
        ldsm4(&Bh[k16][0], sb + OFF_WH + chunk*16384 + off4);
        uint32_t off2 = SWIZ128((uint32_t)(row2*128 + (kc + bsel)*2));
        ldsm2(&Bh[k16][4], sb + OFF_WH + chunk*16384 + off2);
    }

    int arow = wm*16 + (lane & 15);
    int acolsel = (lane >> 4) * 8;
    int jchunk = jcg >> 6;

    float hprev[4] = {0.f, 0.f, 0.f, 0.f};

    // coalesced xw staging: 96 lines of 128B, 3 cp16/thread
    auto xwstage = [&](int tt, int buf) {
#pragma unroll
        for (int q = 0; q < 3; q++) {
            int it = tid + q*256;
            int line = it >> 3, u = it & 7;
            int s = line / 3, g = line - s*3;
            int len_s = slen[s];
            if (tt < len_s) {
                int tk = dir ? (len_s - 1 - tt) : tt;
                const char* src = (const char*)(xw + ((size_t)spb[s]*512 + tk)*1536
                                                + dir*768 + g*256 + j0) + u*16;
                cp16(sb + OFF_XW + (uint32_t)(buf*12800 + s*400 + g*128 + u*16), src);
            }
        }
        asm volatile("cp.async.commit_group;" ::: "memory");
    };
    xwstage(0, 0);

    for (int t = 0; t < tmax; t++) {
        int buf = t & 1;
        // phase 1: cp.async copy of peer-written A tile (single fp16, 16KB)
        size_t tb = ((size_t)((t & 1)*2 + dir)*8 + bt) * 16384;
        const char* srch = (const char*)g_hx + tb;
#pragma unroll
        for (int q = 0; q < 4; q++) {
            int it = (tid + q*256) * 16;
            cp16(sb + OFF_A + it, srch + it);
        }
        asm volatile("cp.async.commit_group;" ::: "memory");
        xwstage(t + 1, buf ^ 1);
        asm volatile("cp.async.wait_group 1;" ::: "memory");
        __syncthreads();

        // phase 2: mma — 1 A ldsm + W-lo (ldsm4+ldsm2) + 6 mma per k16
        float acc[3][4];
#pragma unroll
        for (int g = 0; g < 3; g++) { acc[g][0]=0.f; acc[g][1]=0.f; acc[g][2]=0.f; acc[g][3]=0.f; }
#pragma unroll
        for (int k16 = 0; k16 < 16; k16++) {
            int chunk = k16 >> 2, kc = (k16 & 3)*16;
            uint32_t asw = SWIZ128((uint32_t)(arow*128 + (kc + acolsel)*2));
            uint32_t a4[4];
            ldsm4(a4, sb + OFF_A + chunk*4096 + asw);
            uint32_t bl[6];
            uint32_t off4 = SWIZ128((uint32_t)(row4*128 + (kc + kh4)*2));
            ldsm4(&bl[0], sb + OFF_WL + chunk*16384 + off4);
            uint32_t off2 = SWIZ128((uint32_t)(row2*128 + (kc + bsel)*2));
            ldsm2(&bl[4], sb + OFF_WL + chunk*16384 + off2);
#pragma unroll
            for (int g = 0; g < 3; g++) {
                mma_hf(acc[g], a4, &Bh[k16][g*2]);
                mma_hf(acc[g], a4, &bl[g*2]);
            }
        }

        // phase 3a: gates (xw from smem); update hprev; store peer-consumed h exchange tile
        size_t tbn = ((size_t)(((t+1) & 1)*2 + dir)*8 + bt) * 16384;
        float hy[2][2];
        int tok[2];
#pragma unroll
        for (int si = 0; si < 2; si++) {
            if (t < lenv2[si]) {
                int e = si*2;
                int s = sa + si*8;
                const float* xq = &xsm[buf*3200 + s*100 + jc];
                float2 xrv = *(const float2*)(xq);
                float2 xzv = *(const float2*)(xq + 32);
                float2 xnv = *(const float2*)(xq + 64);
                float r0 = fsig(xrv.x + acc[0][e]   + bhr0);
                float r1 = fsig(xrv.y + acc[0][e+1] + bhr1);
                float z0 = fsig(xzv.x + acc[1][e]   + bhz0);
                float z1 = fsig(xzv.y + acc[1][e+1] + bhz1);
                float n0 = ftanh(xnv.x + r0*(acc[2][e]   + bhn0));
                float n1 = ftanh(xnv.y + r1*(acc[2][e+1] + bhn1));
                float h0 = (1.f - z0)*n0 + z0*hprev[e];
                float h1 = (1.f - z1)*n1 + z1*hprev[e+1];
                hprev[e] = h0; hprev[e+1] = h1;
                hy[si][0] = h0; hy[si][1] = h1;
                uint32_t hp = (uint32_t)__half_as_ushort(__float2half(h0))
                            | ((uint32_t)__half_as_ushort(__float2half(h1)) << 16);
                tok[si] = dir ? (lenv2[si] - 1 - t) : t;
                uint32_t sw = SWIZ128((uint32_t)(s*128 + (jcg & 63)*2));
                *(uint32_t*)((char*)g_hx + tbn + jchunk*4096 + sw) = hp;
            }
        }
        // arrive early (releases our exchange stores), overlap non-peer work, then wait
        asm volatile("barrier.cluster.arrive.aligned;" ::: "memory");
#pragma unroll
        for (int si = 0; si < 2; si++) {
            if (t < lenv2[si]) {
                size_t oc = ((size_t)pb2[si]*512 + tok[si])*512 + dir*256 + jcg;
                if (last) {
                    *(float2*)&y[oc] = make_float2(hy[si][0], hy[si][1]);
                } else {
                    __nv_bfloat16 b0 = __float2bfloat16(hy[si][0]);
                    __nv_bfloat16 b1 = __float2bfloat16(hy[si][1]);
                    __nv_bfloat16 c0 = __float2bfloat16(hy[si][0] - __bfloat162float(b0));
                    __nv_bfloat16 c1 = __float2bfloat16(hy[si][1] - __bfloat162float(b1));
                    *(uint32_t*)&g_ah[oc] = (uint32_t)__bfloat16_as_ushort(b0)
                                          | ((uint32_t)__bfloat16_as_ushort(b1) << 16);
                    *(uint32_t*)&g_al[oc] = (uint32_t)__bfloat16_as_ushort(c0)
                                          | ((uint32_t)__bfloat16_as_ushort(c1) << 16);
                }
            }
        }
        asm volatile("barrier.cluster.wait.aligned;" ::: "memory");
    }
}

// ----------------- top-k pooling + classifier -----------------
__global__ __launch_bounds__(256)
void halt_pool(const float* __restrict__ H, const int* __restrict__ lengths,
               const float* __restrict__ Wc, const float* __restrict__ bc,
               float* __restrict__ out) {
    int b = blockIdx.x, tid = threadIdx.x;
    __shared__ float ns[512];
    __shared__ int   si[512];
    __shared__ float red[256];
    int len = lengths[b];
    int warp = tid >> 5, lane = tid & 31;
    for (int r = warp; r < 512; r += 8) {
        float sc = 1e9f;
        if (r < len) {
            const float* row = H + ((size_t)b*512 + r)*512;
            float acc = 0.f;
#pragma unroll 4
            for (int d = lane; d < 512; d += 32) { float v = row[d]; acc += v*v; }
#pragma unroll
            for (int o = 16; o > 0; o >>= 1) acc += __shfl_xor_sync(0xffffffffu, acc, o);
            sc = -sqrtf(acc);
        }
        if (lane == 0) { ns[r] = sc; si[r] = r; }
    }
    __syncthreads();
    for (int k = 2; k <= 512; k <<= 1)
        for (int j = k >> 1; j > 0; j >>= 1) {
            for (int i = tid; i < 512; i += 256) {
                int ixj = i ^ j;
                if (ixj > i) {
                    bool asc = ((i & k) == 0);
                    float a = ns[i], c = ns[ixj];
                    int ia = si[i], ic = si[ixj];
                    bool gt = (a > c) || (a == c && ia > ic);
                    if (asc == gt) { ns[i] = c; ns[ixj] = a; si[i] = ic; si[ixj] = ia; }
                }
            }
            __syncthreads();
        }
    int kk = (int)ceilf((float)len * 0.15f);
    if (kk < 1) kk = 1;
    float a0 = 0.f, a1 = 0.f;
    for (int i = 0; i < kk; i++) {
        int r = si[i];
        const float* row = H + ((size_t)b*512 + r)*512;
        a0 += row[tid]; a1 += row[tid + 256];
    }
    float kf = (float)kk;
    float part = (a0/kf)*Wc[tid] + (a1/kf)*Wc[tid + 256];
    red[tid] = part;
    __syncthreads();
    for (int s2 = 128; s2 > 0; s2 >>= 1) {
        if (tid < s2) red[tid] += red[tid + s2];
        __syncthreads();
    }
    if (tid == 0) out[b] = red[0] + bc[0];
}

// ----------------- host orchestration -----------------
extern "C" void kernel_launch(void* const* d_in, const int* in_sizes, int n_in,
                              void* d_out, int out_size) {
    const float* x    = (const float*)d_in[0];
    const int*   lens = (const int*)  d_in[1];
    const float* ln_g = (const float*)d_in[2];
    const float* ln_b = (const float*)d_in[3];
    const float* w1   = (const float*)d_in[4];
    const float* b1   = (const float*)d_in[5];
    const float* w2   = (const float*)d_in[6];
    const float* b2   = (const float*)d_in[7];
    const float* Wih0 = (const float*)d_in[8];
    const float* Whh0 = (const float*)d_in[9];
    const float* bih0 = (const float*)d_in[10];
    const float* bhh0 = (const float*)d_in[11];
    const float* Wih  = (const float*)d_in[12];
    const float* Whh  = (const float*)d_in[13];
    const float* bih  = (const float*)d_in[14];
    const float* bhh  = (const float*)d_in[15];
    const float* Wc   = (const float*)d_in[16];
    const float* bc   = (const float*)d_in[17];
    float* out = (float*)d_out;

    cudaFuncSetAttribute(halt_gru3, cudaFuncAttributeMaxDynamicSharedMemorySize, SMEM_G3);
    cudaFuncSetAttribute(halt_tcgemm, cudaFuncAttributeMaxDynamicSharedMemorySize, SMEM_TC);

    void *pB = 0, *pxw = 0, *pwh = 0, *pwl = 0, *phx = 0;
    cudaGetSymbolAddress(&pB,   g_bufB);
    cudaGetSymbolAddress(&pxw,  g_xw);
    cudaGetSymbolAddress(&pwh,  g_wh);
    cudaGetSymbolAddress(&pwl,  g_wl);
    cudaGetSymbolAddress(&phx,  g_hx);
    float* fB  = (float*)pB;
    float* fxw = (float*)pxw;

    halt_sort_perm<<<1, 256>>>(lens);
    halt_proj<<<NT, 128>>>(x, lens, ln_g, ln_b, w1, b1, w2, b2);

    for (int l = 0; l < 5; l++) {
        const float* Wi = l ? (Wih + (size_t)(l-1)*2*768*512) : Wih0;
        int K = l ? 512 : 128;
        size_t nW = (size_t)1536 * K;
        __nv_bfloat16* wh = (__nv_bfloat16*)pwh + (size_t)l*1536*512;
        __nv_bfloat16* wl = (__nv_bfloat16*)pwl + (size_t)l*1536*512;
        halt_cvt<<<(unsigned)((nW + 255)/256), 256>>>(Wi, wh, wl, nW);
    }

    for (int l = 0; l < 5; l++) {
        const float* bi = l ? (bih + (l-1)*1536) : bih0;
        const float* Wh = l ? (Whh + (size_t)(l-1)*2*768*256) : Whh0;
        const float* bh = l ? (bhh + (l-1)*1536) : bhh0;
        int K = l ? 512 : 128;
        const __nv_bfloat16* wh = (const __nv_bfloat16*)pwh + (size_t)l*1536*512;
        const __nv_bfloat16* wl = (const __nv_bfloat16*)pwl + (size_t)l*1536*512;

        cudaMemsetAsync(phx, 0, (size_t)2*2*8*4*32*64*sizeof(__half));

        dim3 gg(NT/128, 6);
        halt_tcgemm<<<gg, 256, SMEM_TC>>>(K, wh, wl, bi, lens);

        halt_gru3<<<128, 256, SMEM_G3>>>(fxw, fB, Wh, bh, lens, (l == 4) ? 1 : 0);
    }
    halt_pool<<<256, 256>>>(fB, lens, Wc, bc, out);
}